// round 13
// baseline (speedup 1.0000x reference)
#include <cuda_runtime.h>
#include <math.h>
#include <stdint.h>

#define BB   4
#define QQ   512
#define KKT  1024
#define DD   512
#define HH   8
#define DH   64
#define DFF  2048
#define NL   12
#define NV   332
#define MEML 512
#define UW   128
#define RKP  (KKT + UW)

// ---------------- scratch ----------------
__device__ float g_h[BB*QQ*DD];
__device__ float g_norm[BB*QQ*DD];
__device__ float g_wh[BB*QQ*3*DD];
__device__ float g_whmem[3*DD];
__device__ float g_posemb[KKT*DD];
__device__ float g_rk[KKT*DD];
__device__ float g_rkt[HH*RKP*DH];
__device__ float g_vt[BB*HH*DH*QQ];
__device__ float g_c0[BB*HH*QQ];
__device__ float g_bwl[BB*HH*QQ];
__device__ float g_br[HH*RKP];
__device__ float g_attn[BB*QQ*DD];
__device__ float g_ff[BB*QQ*DFF];
__device__ float g_gath[BB*QQ*DD];

__device__ __forceinline__ float to_tf32(float x) {
    uint32_t u;
    asm("cvt.rna.tf32.f32 %0, %1;" : "=r"(u) : "f"(x));
    return __uint_as_float(u);
}
__device__ __forceinline__ uint32_t to_tf32u(float x) {
    uint32_t u;
    asm("cvt.rna.tf32.f32 %0, %1;" : "=r"(u) : "f"(x));
    return u;
}

#define MMA_TF32(acc, a0,a1,a2,a3, b0,b1) \
    asm volatile("mma.sync.aligned.m16n8k8.row.col.f32.tf32.tf32.f32 " \
                 "{%0,%1,%2,%3}, {%4,%5,%6,%7}, {%8,%9}, {%0,%1,%2,%3};" \
                 : "+f"(acc[0]), "+f"(acc[1]), "+f"(acc[2]), "+f"(acc[3]) \
                 : "r"(a0), "r"(a1), "r"(a2), "r"(a3), "r"(b0), "r"(b1))

// ---------------- templated tf32 GEMM ----------------
// Per-warp tile: (MT*16) x (NT*8). Warps laid out (TT/32/NW_N) x NW_N where
// NW_N = BNT/(NT*8).
template<int BMT, int BNT, int TT, int MB, int MT, int NT>
__global__ __launch_bounds__(TT, MB)
void gemm_t(const float* __restrict__ A, const float* __restrict__ B,
            float* __restrict__ C,
            int M, int N, int Kd, int ldc,
            const float* __restrict__ addsrc, int ldadd,
            const float* __restrict__ bias,
            float alpha, int relu)
{
    constexpr int R4 = TT / 4;
    constexpr int IA = (BMT + R4 - 1) / R4;
    constexpr int IB = (BNT + R4 - 1) / R4;
    constexpr int NW_N = BNT / (NT * 8);

    __shared__ float As[2][BMT][20];
    __shared__ float Bs[2][BNT][20];

    int bm = blockIdx.y * BMT, bn = blockIdx.x * BNT;
    int tid  = threadIdx.x;
    int lane = tid & 31, warp = tid >> 5;
    int g  = lane >> 2, t4 = lane & 3;
    int wm = (warp / NW_N) * (MT * 16);
    int wn = (warp % NW_N) * (NT * 8);

    int lrow = tid >> 2;
    int lkq  = (tid & 3) * 4;

    float acc[MT][NT][4];
#pragma unroll
    for (int mt = 0; mt < MT; mt++)
#pragma unroll
        for (int nt = 0; nt < NT; nt++)
#pragma unroll
            for (int q = 0; q < 4; q++) acc[mt][nt][q] = 0.f;

    float4 pa[IA], pb[IB];

    auto ldgA = [&](int k0, int it) -> float4 {
        int r = lrow + it * R4;
        int gm = bm + r;
        if (r < BMT && gm < M) return *(const float4*)&A[(long long)gm * Kd + k0 + lkq];
        return make_float4(0.f, 0.f, 0.f, 0.f);
    };
    auto ldgB = [&](int k0, int it) -> float4 {
        int r = lrow + it * R4;
        int gn = bn + r;
        if (r < BNT && gn < N) return *(const float4*)&B[(long long)gn * Kd + k0 + lkq];
        return make_float4(0.f, 0.f, 0.f, 0.f);
    };
    auto stash = [&](int buf) {
#pragma unroll
        for (int it = 0; it < IA; it++) {
            int r = lrow + it * R4;
            if (r < BMT) {
                float4 ta = make_float4(to_tf32(pa[it].x), to_tf32(pa[it].y),
                                        to_tf32(pa[it].z), to_tf32(pa[it].w));
                *(float4*)&As[buf][r][lkq] = ta;
            }
        }
#pragma unroll
        for (int it = 0; it < IB; it++) {
            int r = lrow + it * R4;
            if (r < BNT) {
                float4 tb = make_float4(to_tf32(pb[it].x), to_tf32(pb[it].y),
                                        to_tf32(pb[it].z), to_tf32(pb[it].w));
                *(float4*)&Bs[buf][r][lkq] = tb;
            }
        }
    };

    int nk = Kd >> 4;
#pragma unroll
    for (int it = 0; it < IA; it++) pa[it] = ldgA(0, it);
#pragma unroll
    for (int it = 0; it < IB; it++) pb[it] = ldgB(0, it);
    stash(0);
    __syncthreads();

    int buf = 0;
    for (int t = 0; t < nk; t++) {
        int has_next = (t + 1 < nk);
        if (has_next) {
            int k0 = (t + 1) << 4;
#pragma unroll
            for (int it = 0; it < IA; it++) pa[it] = ldgA(k0, it);
#pragma unroll
            for (int it = 0; it < IB; it++) pb[it] = ldgB(k0, it);
        }
#pragma unroll
        for (int ks = 0; ks < 16; ks += 8) {
            uint32_t af[MT][4];
#pragma unroll
            for (int mt = 0; mt < MT; mt++) {
                int m0 = wm + mt * 16 + g;
                af[mt][0] = __float_as_uint(As[buf][m0    ][ks + t4    ]);
                af[mt][1] = __float_as_uint(As[buf][m0 + 8][ks + t4    ]);
                af[mt][2] = __float_as_uint(As[buf][m0    ][ks + t4 + 4]);
                af[mt][3] = __float_as_uint(As[buf][m0 + 8][ks + t4 + 4]);
            }
#pragma unroll
            for (int nt = 0; nt < NT; nt++) {
                int n0 = wn + nt * 8 + g;
                uint32_t b0 = __float_as_uint(Bs[buf][n0][ks + t4    ]);
                uint32_t b1 = __float_as_uint(Bs[buf][n0][ks + t4 + 4]);
#pragma unroll
                for (int mt = 0; mt < MT; mt++)
                    MMA_TF32(acc[mt][nt], af[mt][0], af[mt][1], af[mt][2], af[mt][3], b0, b1);
            }
        }
        if (has_next) {
            stash(buf ^ 1);
            __syncthreads();
            buf ^= 1;
        }
    }

    auto emit = [&](int gm, int gn, float v) {
        if (gm < M && gn < N) {
            v *= alpha;
            if (bias) v += bias[gn];
            if (relu) v = fmaxf(v, 0.f);
            if (addsrc) v += addsrc[(long long)gm * ldadd + gn];
            C[(long long)gm * ldc + gn] = v;
        }
    };
#pragma unroll
    for (int mt = 0; mt < MT; mt++) {
        int r0 = bm + wm + mt * 16 + g;
#pragma unroll
        for (int nt = 0; nt < NT; nt++) {
            int c0 = bn + wn + nt * 8 + t4 * 2;
            emit(r0,     c0,     acc[mt][nt][0]);
            emit(r0,     c0 + 1, acc[mt][nt][1]);
            emit(r0 + 8, c0,     acc[mt][nt][2]);
            emit(r0 + 8, c0 + 1, acc[mt][nt][3]);
        }
    }
}

// ---------------- fused flash attention (exact R5/R8) ----------------
#define SQS 68
#define STS 84

__global__ __launch_bounds__(128, 2)
void attn_kernel()
{
    extern __shared__ float sm[];
    float* sK  = sm;
    float* sV  = sK + 64 * SQS;
    float* sRK = sV + 64 * SQS;
    float* sT  = sRK + UW * SQS;
    float* sBW = sT + 64 * STS;
    float* sBR = sBW + 64;
    float* sC0 = sBR + 128;

    int it = blockIdx.x;
    int bh = blockIdx.y;
    int h = bh & 7, b = bh >> 3;
    int i0 = it * 64;
    int tid = threadIdx.x, lane = tid & 31, warp = tid >> 5;
    int g = lane >> 2, t4 = lane & 3;
    int wr = warp * 16;
    int nt0w = 6 - 2 * warp;

    const float* RKg = g_rkt + (long long)h * RKP * DH;
    const float* Vtg = g_vt + (long long)bh * DH * QQ;

    uint32_t afQ[8][4];
    {
        long long qb = (long long)(b * QQ + i0) * (3 * DD) + h * 64;
        const float* q0 = g_wh + qb + (long long)(wr + g) * (3 * DD);
        const float* q1 = g_wh + qb + (long long)(wr + g + 8) * (3 * DD);
#pragma unroll
        for (int ks = 0; ks < 8; ks++) {
            afQ[ks][0] = to_tf32u(q0[ks * 8 + t4]);
            afQ[ks][1] = to_tf32u(q1[ks * 8 + t4]);
            afQ[ks][2] = to_tf32u(q0[ks * 8 + t4 + 4]);
            afQ[ks][3] = to_tf32u(q1[ks * 8 + t4 + 4]);
        }
    }
    if (tid < 64) sC0[tid] = g_c0[bh * QQ + i0 + tid];

    float mrow[2] = {-1e30f, -1e30f};
    float lrow[2] = {0.f, 0.f};
    float msum[2] = {0.f, 0.f};
    float O[8][4];
#pragma unroll
    for (int nt = 0; nt < 8; nt++)
#pragma unroll
        for (int q = 0; q < 4; q++) O[nt][q] = 0.f;

    int njt = it + 9;
    for (int jt = 0; jt < njt; jt++) {
        int j0 = jt * 64;
        int mem = (jt < 8);
        int ub = j0 - i0 + 448;
        __syncthreads();
        {
            const float* rs = RKg + (long long)(ub + tid) * DH;
            float* rd = sRK + tid * SQS;
#pragma unroll
            for (int q = 0; q < 16; q++) {
                float4 v = *(const float4*)(rs + q * 4);
                rd[q*4+0] = to_tf32(v.x); rd[q*4+1] = to_tf32(v.y);
                rd[q*4+2] = to_tf32(v.z); rd[q*4+3] = to_tf32(v.w);
            }
        }
        if (!mem) {
            int r = tid >> 1, half = (tid & 1) * 32;
            const float* ksrc = g_wh + (long long)(b * QQ + j0 - MEML + r) * (3 * DD) + DD + h * 64 + half;
            float* kd = sK + r * SQS + half;
            const float* vsrc = Vtg + (long long)r * QQ + (j0 - MEML) + half;
            float* vd = sV + r * SQS + half;
#pragma unroll
            for (int q = 0; q < 8; q++) {
                float4 v = *(const float4*)(ksrc + q * 4);
                kd[q*4+0] = to_tf32(v.x); kd[q*4+1] = to_tf32(v.y);
                kd[q*4+2] = to_tf32(v.z); kd[q*4+3] = to_tf32(v.w);
                float4 w = *(const float4*)(vsrc + q * 4);
                vd[q*4+0] = to_tf32(w.x); vd[q*4+1] = to_tf32(w.y);
                vd[q*4+2] = to_tf32(w.z); vd[q*4+3] = to_tf32(w.w);
            }
            if (tid < 64) sBW[tid] = g_bwl[bh * QQ + (j0 - MEML) + tid];
        }
        sBR[tid] = g_br[h * RKP + ub + tid];
        __syncthreads();

        float ac[8][4];
        float tf[10][4];
#pragma unroll
        for (int nt = 0; nt < 8; nt++)
#pragma unroll
            for (int q = 0; q < 4; q++) ac[nt][q] = 0.f;
#pragma unroll
        for (int nt = 0; nt < 10; nt++)
#pragma unroll
            for (int q = 0; q < 4; q++) tf[nt][q] = 0.f;

#pragma unroll
        for (int ks = 0; ks < 8; ks++) {
            uint32_t a0 = afQ[ks][0], a1 = afQ[ks][1], a2 = afQ[ks][2], a3 = afQ[ks][3];
            if (!mem) {
#pragma unroll
                for (int nt = 0; nt < 8; nt++) {
                    uint32_t b0 = __float_as_uint(sK[(nt * 8 + g) * SQS + ks * 8 + t4    ]);
                    uint32_t b1 = __float_as_uint(sK[(nt * 8 + g) * SQS + ks * 8 + t4 + 4]);
                    MMA_TF32(ac[nt], a0, a1, a2, a3, b0, b1);
                }
            }
#pragma unroll
            for (int nt = 0; nt < 10; nt++) {
                int u = (nt0w + nt) * 8 + g;
                uint32_t b0 = __float_as_uint(sRK[u * SQS + ks * 8 + t4    ]);
                uint32_t b1 = __float_as_uint(sRK[u * SQS + ks * 8 + t4 + 4]);
                MMA_TF32(tf[nt], a0, a1, a2, a3, b0, b1);
            }
        }
        __syncthreads();

#pragma unroll
        for (int nt = 0; nt < 10; nt++) {
            int cr = nt * 8 + t4 * 2;
            sT[(wr + g    ) * STS + cr    ] = tf[nt][0];
            sT[(wr + g    ) * STS + cr + 1] = tf[nt][1];
            sT[(wr + g + 8) * STS + cr    ] = tf[nt][2];
            sT[(wr + g + 8) * STS + cr + 1] = tf[nt][3];
        }
        __syncwarp();

        int last = (jt == it + 8);
        float mt2[2] = {-1e30f, -1e30f};
#pragma unroll
        for (int nt = 0; nt < 8; nt++) {
            int jl0 = nt * 8 + t4 * 2;
#pragma unroll
            for (int r2 = 0; r2 < 2; r2++) {
                int il = wr + g + r2 * 8;
#pragma unroll
                for (int cc = 0; cc < 2; cc++) {
                    int jl = jl0 + cc;
                    int crel = jl - g - r2 * 8 + 15;
                    float base = mem ? sC0[il] : (ac[nt][r2*2+cc] + sBW[jl]);
                    float s = (base + sT[il * STS + crel] + sBR[jl - il + 63]) * 0.125f;
                    if (last && jl > il) s = -1e30f;
                    ac[nt][r2*2+cc] = s;
                    mt2[r2] = fmaxf(mt2[r2], s);
                }
            }
        }
#pragma unroll
        for (int r2 = 0; r2 < 2; r2++) {
            mt2[r2] = fmaxf(mt2[r2], __shfl_xor_sync(0xffffffffu, mt2[r2], 1));
            mt2[r2] = fmaxf(mt2[r2], __shfl_xor_sync(0xffffffffu, mt2[r2], 2));
        }
        float corr[2], ls[2] = {0.f, 0.f};
#pragma unroll
        for (int r2 = 0; r2 < 2; r2++) {
            float mnew = fmaxf(mrow[r2], mt2[r2]);
            corr[r2] = __expf(mrow[r2] - mnew);
            mrow[r2] = mnew;
        }
#pragma unroll
        for (int nt = 0; nt < 8; nt++)
#pragma unroll
            for (int r2 = 0; r2 < 2; r2++)
#pragma unroll
                for (int cc = 0; cc < 2; cc++) {
                    float e = __expf(ac[nt][r2*2+cc] - mrow[r2]);
                    ac[nt][r2*2+cc] = e;
                    ls[r2] += e;
                }
#pragma unroll
        for (int r2 = 0; r2 < 2; r2++) {
            ls[r2] += __shfl_xor_sync(0xffffffffu, ls[r2], 1);
            ls[r2] += __shfl_xor_sync(0xffffffffu, ls[r2], 2);
            lrow[r2] = lrow[r2] * corr[r2] + ls[r2];
            msum[r2] *= corr[r2];
            if (mem) msum[r2] += ls[r2];
        }
#pragma unroll
        for (int nt = 0; nt < 8; nt++)
#pragma unroll
            for (int q = 0; q < 4; q++) O[nt][q] *= corr[q >> 1];

        if (!mem) {
#pragma unroll
            for (int nt = 0; nt < 8; nt++) {
                int c = nt * 8 + t4 * 2;
                sRK[(wr + g    ) * SQS + c    ] = to_tf32(ac[nt][0]);
                sRK[(wr + g    ) * SQS + c + 1] = to_tf32(ac[nt][1]);
                sRK[(wr + g + 8) * SQS + c    ] = to_tf32(ac[nt][2]);
                sRK[(wr + g + 8) * SQS + c + 1] = to_tf32(ac[nt][3]);
            }
            __syncwarp();
#pragma unroll
            for (int ks = 0; ks < 8; ks++) {
                uint32_t a0 = __float_as_uint(sRK[(wr + g    ) * SQS + ks * 8 + t4    ]);
                uint32_t a1 = __float_as_uint(sRK[(wr + g + 8) * SQS + ks * 8 + t4    ]);
                uint32_t a2 = __float_as_uint(sRK[(wr + g    ) * SQS + ks * 8 + t4 + 4]);
                uint32_t a3 = __float_as_uint(sRK[(wr + g + 8) * SQS + ks * 8 + t4 + 4]);
#pragma unroll
                for (int nt = 0; nt < 8; nt++) {
                    uint32_t b0 = __float_as_uint(sV[(nt * 8 + g) * SQS + ks * 8 + t4    ]);
                    uint32_t b1 = __float_as_uint(sV[(nt * 8 + g) * SQS + ks * 8 + t4 + 4]);
                    MMA_TF32(O[nt], a0, a1, a2, a3, b0, b1);
                }
            }
        }
    }

    float inv0 = 1.f / lrow[0], inv1 = 1.f / lrow[1];
    const float* vm = g_whmem + 2 * DD + h * 64;
    long long r0 = (long long)(b * QQ + i0 + wr + g) * DD + h * 64;
    long long r1 = (long long)(b * QQ + i0 + wr + g + 8) * DD + h * 64;
#pragma unroll
    for (int nt = 0; nt < 8; nt++) {
        int c = nt * 8 + t4 * 2;
        float v0 = vm[c], v1 = vm[c + 1];
        g_attn[r0 + c]     = (O[nt][0] + msum[0] * v0) * inv0;
        g_attn[r0 + c + 1] = (O[nt][1] + msum[0] * v1) * inv0;
        g_attn[r1 + c]     = (O[nt][2] + msum[1] * v0) * inv1;
        g_attn[r1 + c + 1] = (O[nt][3] + msum[1] * v1) * inv1;
    }
}

// ---------------- layernorm (vectorized, 2 rows/block) ----------------
__global__ void ln_kernel(const float* __restrict__ x, float* __restrict__ y,
                          const float* __restrict__ g, const float* __restrict__ b)
{
    int tid = threadIdx.x;
    int half = tid >> 7;
    int t = tid & 127;
    int row = blockIdx.x * 2 + half;
    const float* xr = x + (long long)row * DD;
    float* yr = y + (long long)row * DD;
    float4 v = *(const float4*)(xr + t * 4);
    float s = v.x + v.y + v.z + v.w;
    float s2 = v.x*v.x + v.y*v.y + v.z*v.z + v.w*v.w;
    __shared__ float sh[2][8];
    __shared__ float stats[2][2];
#pragma unroll
    for (int o = 16; o > 0; o >>= 1) {
        s  += __shfl_xor_sync(0xffffffffu, s,  o);
        s2 += __shfl_xor_sync(0xffffffffu, s2, o);
    }
    int w4 = (tid >> 5) & 3;
    if ((tid & 31) == 0) { sh[half][w4] = s; sh[half][w4 + 4] = s2; }
    __syncthreads();
    if (t == 0) {
        float S = sh[half][0] + sh[half][1] + sh[half][2] + sh[half][3];
        float S2 = sh[half][4] + sh[half][5] + sh[half][6] + sh[half][7];
        float mu = S / DD;
        float var = S2 / DD - mu * mu;
        stats[half][0] = mu;
        stats[half][1] = rsqrtf(var + 1e-3f);
    }
    __syncthreads();
    float mu = stats[half][0], rs = stats[half][1];
    float4 gv = *(const float4*)(g + t * 4);
    float4 bv = *(const float4*)(b + t * 4);
    float4 o;
    o.x = (v.x - mu) * rs * gv.x + bv.x;
    o.y = (v.y - mu) * rs * gv.y + bv.y;
    o.z = (v.z - mu) * rs * gv.z + bv.z;
    o.w = (v.w - mu) * rs * gv.w + bv.w;
    *(float4*)(yr + t * 4) = o;
}

__global__ void whmem_kernel(const float* __restrict__ qkvw, const float* __restrict__ lnb)
{
    int n = blockIdx.x * blockDim.x + threadIdx.x;
    if (n >= 3 * DD) return;
    const float* wr = qkvw + (long long)n * DD;
    float s = 0.f;
    for (int c = 0; c < DD; c++) s += lnb[c] * wr[c];
    g_whmem[n] = s;
}

__global__ void posemb_kernel()
{
    int idx = blockIdx.x * blockDim.x + threadIdx.x;
    if (idx >= KKT * DD) return;
    int p = idx / DD, c = idx % DD;
    float pos = (float)(KKT - 1 - p);
    int k = (c < 256) ? c : (c - 256);
    float invf = powf(10000.0f, -((float)(2 * k)) / 512.0f);
    float a = pos * invf;
    g_posemb[idx] = (c < 256) ? sinf(a) : cosf(a);
}

__global__ void gather_kernel(const int* __restrict__ ids, const float* __restrict__ emb)
{
    int idx = blockIdx.x * blockDim.x + threadIdx.x;
    if (idx >= BB * QQ * DD) return;
    int m = idx / DD, c = idx % DD;
    g_gath[idx] = emb[(long long)ids[m] * DD + c];
}

// ---------------- merged attention-prep kernel (regions A-D) ----------------
#define PREP_A 2304
#define PREP_B (PREP_A + 4096)
#define PREP_C (PREP_B + 36)
#define PREP_D (PREP_C + 8192)

__global__ void prep_kernel(const float* __restrict__ rwb, const float* __restrict__ rrb)
{
    int blk = blockIdx.x;
    int tid = threadIdx.x;
    if (blk < PREP_A) {
        int idx = blk * 256 + tid;
        int d = idx & 63;
        int p = (idx >> 6) % RKP;
        int h = idx / (RKP * DH);
        g_rkt[idx] = (p < KKT) ? g_rk[(long long)p * DD + h * 64 + d] : 0.f;
    } else if (blk < PREP_B) {
        int idx = (blk - PREP_A) * 256 + tid;
        int jq = idx & 511;
        int d  = (idx >> 9) & 63;
        int bh = idx >> 15;
        int b = bh >> 3, h = bh & 7;
        g_vt[idx] = g_wh[(long long)(b * QQ + jq) * (3 * DD) + 2 * DD + h * 64 + d];
    } else if (blk < PREP_C) {
        int idx = (blk - PREP_B) * 256 + tid;
        if (idx >= HH * RKP) return;
        int h = idx / RKP, u = idx % RKP;
        float s = 0.f;
        if (u < KKT) {
            const float* rr = g_rk + (long long)u * DD + h * 64;
            const float* w = rrb + h * DH;
#pragma unroll
            for (int d = 0; d < DH; d++) s += w[d] * rr[d];
        }
        g_br[idx] = s;
    } else {
        int unit = tid >> 6;
        int t = tid & 63;
        int row = (blk - PREP_C) * 4 + unit;
        int kind = row >> 14;
        int r = row & 16383;
        int bh = r >> 9, iq = r & 511;
        int h = bh & 7, b = bh >> 3;
        long long base = (long long)(b * QQ + iq) * (3 * DD) + h * 64;
        float v;
        if (kind == 0) {
            v = (g_wh[base + t] + rwb[h * 64 + t]) * g_whmem[DD + h * 64 + t];
        } else {
            v = rwb[h * 64 + t] * g_wh[base + DD + t];
        }
#pragma unroll
        for (int o = 16; o > 0; o >>= 1) v += __shfl_xor_sync(0xffffffffu, v, o);
        __shared__ float sh[8];
        if ((t & 31) == 0) sh[unit * 2 + (t >> 5)] = v;
        __syncthreads();
        if (t == 0) {
            float s = sh[unit * 2] + sh[unit * 2 + 1];
            if (kind == 0) g_c0[r] = s; else g_bwl[r] = s;
        }
    }
}

// ---------------- host ----------------
static void gemm(const float* A, const float* B, float* C,
                 int M, int N, int K, int ldc,
                 const float* add, int ldadd, const float* bias,
                 float alpha, int relu)
{
    // 64x64 tiles everywhere: max block count, 4 blocks/SM, L2-resident operands
    dim3 grid((N + 63) / 64, (M + 63) / 64);
    gemm_t<64, 64, 128, 4, 2, 4><<<grid, 128>>>(A, B, C, M, N, K, ldc,
                                                add, ldadd, bias, alpha, relu);
}

extern "C" void kernel_launch(void* const* d_in, const int* in_sizes, int n_in,
                              void* d_out, int out_size)
{
    const int*   ids      = (const int*)d_in[0];
    const float* emb      = (const float*)d_in[1];
    const float* emb_proj = (const float*)d_in[2];
    const float* rwb      = (const float*)d_in[3];
    const float* rrb      = (const float*)d_in[4];
    const float* qkv_w    = (const float*)d_in[5];
    const float* o_w      = (const float*)d_in[6];
    const float* rnet_w   = (const float*)d_in[7];
    const float* ln1g     = (const float*)d_in[8];
    const float* ln1b     = (const float*)d_in[9];
    const float* ff1w     = (const float*)d_in[10];
    const float* ff1b     = (const float*)d_in[11];
    const float* ff2w     = (const float*)d_in[12];
    const float* ff2b     = (const float*)d_in[13];
    const float* ln2g     = (const float*)d_in[14];
    const float* ln2b     = (const float*)d_in[15];
    const float* headw    = (const float*)d_in[16];
    const float* headb    = (const float*)d_in[17];
    float* out = (float*)d_out;

    float *p_h, *p_norm, *p_wh, *p_posemb, *p_rk, *p_attn, *p_ff, *p_gath;
    void* tmp;
#define SYM(v, s) cudaGetSymbolAddress(&tmp, s); v = (float*)tmp;
    SYM(p_h, g_h) SYM(p_norm, g_norm) SYM(p_wh, g_wh) SYM(p_posemb, g_posemb)
    SYM(p_rk, g_rk) SYM(p_attn, g_attn) SYM(p_ff, g_ff) SYM(p_gath, g_gath)
#undef SYM

    const int ATTN_SMEM = (2 * 64 * SQS + UW * SQS + 64 * STS + 64 + 128 + 64) * 4;
    cudaFuncSetAttribute(attn_kernel, cudaFuncAttributeMaxDynamicSharedMemorySize, ATTN_SMEM);

    const int MQ = BB * QQ;

    gather_kernel<<<(MQ * DD + 255) / 256, 256>>>(ids, emb);
    posemb_kernel<<<(KKT * DD + 255) / 256, 256>>>();
    gemm(p_gath, emb_proj, p_h, MQ, DD, DD, DD,
         nullptr, 0, nullptr, sqrtf((float)DD), 0);

    for (int l = 0; l < NL; l++) {
        const float* qkvw_l = qkv_w + (long long)l * 3 * DD * DD;
        const float* ow_l   = o_w   + (long long)l * DD * DD;
        const float* rnw_l  = rnet_w+ (long long)l * DD * DD;
        const float* f1w_l  = ff1w  + (long long)l * DFF * DD;
        const float* f1b_l  = ff1b  + (long long)l * DFF;
        const float* f2w_l  = ff2w  + (long long)l * DD * DFF;
        const float* f2b_l  = ff2b  + (long long)l * DD;

        ln_kernel<<<MQ / 2, 256>>>(p_h, p_norm, ln1g + l * DD, ln1b + l * DD);
        whmem_kernel<<<12, 128>>>(qkvw_l, ln1b + l * DD);
        gemm(p_norm, qkvw_l, p_wh, MQ, 3 * DD, DD, 3 * DD,
             nullptr, 0, nullptr, 1.f, 0);

        gemm(p_posemb, rnw_l, p_rk, KKT, DD, DD, DD,
             nullptr, 0, nullptr, 1.f, 0);

        prep_kernel<<<PREP_D, 256>>>(rwb, rrb);

        attn_kernel<<<dim3(QQ / 64, BB * HH), 128, ATTN_SMEM>>>();

        gemm(p_attn, ow_l, p_h, MQ, DD, DD, DD,
             p_h, DD, nullptr, 1.f, 0);

        ln_kernel<<<MQ / 2, 256>>>(p_h, p_norm, ln2g + l * DD, ln2b + l * DD);
        gemm(p_norm, f1w_l, p_ff, MQ, DFF, DD, DFF,
             nullptr, 0, f1b_l, 1.f, 1);
        gemm(p_ff, f2w_l, p_h, MQ, DD, DFF, DD,
             p_h, DD, f2b_l, 1.f, 0);
    }

    gemm(p_h, headw, out, MQ, NV, DD, NV,
         nullptr, 0, headb, 1.f, 0);
}

// round 14
// speedup vs baseline: 1.0454x; 1.0454x over previous
#include <cuda_runtime.h>
#include <math.h>
#include <stdint.h>

#define BB   4
#define QQ   512
#define KKT  1024
#define DD   512
#define HH   8
#define DH   64
#define DFF  2048
#define NL   12
#define NV   332
#define MEML 512
#define UW   128
#define RKP  (KKT + UW)

// ---------------- scratch ----------------
__device__ float g_h[BB*QQ*DD];
__device__ float g_norm[BB*QQ*DD];
__device__ float g_wh[BB*QQ*3*DD];
__device__ float g_whmem[3*DD];
__device__ float g_posemb[KKT*DD];
__device__ float g_rk[KKT*DD];
__device__ float g_rkt[HH*RKP*DH];
__device__ float g_vt[BB*HH*DH*QQ];
__device__ float g_c0[BB*HH*QQ];
__device__ float g_bwl[BB*HH*QQ];
__device__ float g_br[HH*RKP];
__device__ float g_attn[BB*QQ*DD];
__device__ float g_ff[BB*QQ*DFF];
__device__ float g_gath[BB*QQ*DD];

__device__ __forceinline__ float to_tf32(float x) {
    uint32_t u;
    asm("cvt.rna.tf32.f32 %0, %1;" : "=r"(u) : "f"(x));
    return __uint_as_float(u);
}
__device__ __forceinline__ uint32_t to_tf32u(float x) {
    uint32_t u;
    asm("cvt.rna.tf32.f32 %0, %1;" : "=r"(u) : "f"(x));
    return u;
}

#define MMA_TF32(acc, a0,a1,a2,a3, b0,b1) \
    asm volatile("mma.sync.aligned.m16n8k8.row.col.f32.tf32.tf32.f32 " \
                 "{%0,%1,%2,%3}, {%4,%5,%6,%7}, {%8,%9}, {%0,%1,%2,%3};" \
                 : "+f"(acc[0]), "+f"(acc[1]), "+f"(acc[2]), "+f"(acc[3]) \
                 : "r"(a0), "r"(a1), "r"(a2), "r"(a3), "r"(b0), "r"(b1))

// ---------------- templated tf32 GEMM ----------------
// Per-warp tile: (MT*16) x (NT*8). Warps laid out (TT/32/NW_N) x NW_N where
// NW_N = BNT/(NT*8).
template<int BMT, int BNT, int TT, int MB, int MT, int NT>
__global__ __launch_bounds__(TT, MB)
void gemm_t(const float* __restrict__ A, const float* __restrict__ B,
            float* __restrict__ C,
            int M, int N, int Kd, int ldc,
            const float* __restrict__ addsrc, int ldadd,
            const float* __restrict__ bias,
            float alpha, int relu)
{
    constexpr int R4 = TT / 4;
    constexpr int IA = (BMT + R4 - 1) / R4;
    constexpr int IB = (BNT + R4 - 1) / R4;
    constexpr int NW_N = BNT / (NT * 8);

    __shared__ float As[2][BMT][20];
    __shared__ float Bs[2][BNT][20];

    int bm = blockIdx.y * BMT, bn = blockIdx.x * BNT;
    int tid  = threadIdx.x;
    int lane = tid & 31, warp = tid >> 5;
    int g  = lane >> 2, t4 = lane & 3;
    int wm = (warp / NW_N) * (MT * 16);
    int wn = (warp % NW_N) * (NT * 8);

    int lrow = tid >> 2;
    int lkq  = (tid & 3) * 4;

    float acc[MT][NT][4];
#pragma unroll
    for (int mt = 0; mt < MT; mt++)
#pragma unroll
        for (int nt = 0; nt < NT; nt++)
#pragma unroll
            for (int q = 0; q < 4; q++) acc[mt][nt][q] = 0.f;

    float4 pa[IA], pb[IB];

    auto ldgA = [&](int k0, int it) -> float4 {
        int r = lrow + it * R4;
        int gm = bm + r;
        if (r < BMT && gm < M) return *(const float4*)&A[(long long)gm * Kd + k0 + lkq];
        return make_float4(0.f, 0.f, 0.f, 0.f);
    };
    auto ldgB = [&](int k0, int it) -> float4 {
        int r = lrow + it * R4;
        int gn = bn + r;
        if (r < BNT && gn < N) return *(const float4*)&B[(long long)gn * Kd + k0 + lkq];
        return make_float4(0.f, 0.f, 0.f, 0.f);
    };
    auto stash = [&](int buf) {
#pragma unroll
        for (int it = 0; it < IA; it++) {
            int r = lrow + it * R4;
            if (r < BMT) {
                float4 ta = make_float4(to_tf32(pa[it].x), to_tf32(pa[it].y),
                                        to_tf32(pa[it].z), to_tf32(pa[it].w));
                *(float4*)&As[buf][r][lkq] = ta;
            }
        }
#pragma unroll
        for (int it = 0; it < IB; it++) {
            int r = lrow + it * R4;
            if (r < BNT) {
                float4 tb = make_float4(to_tf32(pb[it].x), to_tf32(pb[it].y),
                                        to_tf32(pb[it].z), to_tf32(pb[it].w));
                *(float4*)&Bs[buf][r][lkq] = tb;
            }
        }
    };

    int nk = Kd >> 4;
#pragma unroll
    for (int it = 0; it < IA; it++) pa[it] = ldgA(0, it);
#pragma unroll
    for (int it = 0; it < IB; it++) pb[it] = ldgB(0, it);
    stash(0);
    __syncthreads();

    int buf = 0;
    for (int t = 0; t < nk; t++) {
        int has_next = (t + 1 < nk);
        if (has_next) {
            int k0 = (t + 1) << 4;
#pragma unroll
            for (int it = 0; it < IA; it++) pa[it] = ldgA(k0, it);
#pragma unroll
            for (int it = 0; it < IB; it++) pb[it] = ldgB(k0, it);
        }
#pragma unroll
        for (int ks = 0; ks < 16; ks += 8) {
            uint32_t af[MT][4];
#pragma unroll
            for (int mt = 0; mt < MT; mt++) {
                int m0 = wm + mt * 16 + g;
                af[mt][0] = __float_as_uint(As[buf][m0    ][ks + t4    ]);
                af[mt][1] = __float_as_uint(As[buf][m0 + 8][ks + t4    ]);
                af[mt][2] = __float_as_uint(As[buf][m0    ][ks + t4 + 4]);
                af[mt][3] = __float_as_uint(As[buf][m0 + 8][ks + t4 + 4]);
            }
#pragma unroll
            for (int nt = 0; nt < NT; nt++) {
                int n0 = wn + nt * 8 + g;
                uint32_t b0 = __float_as_uint(Bs[buf][n0][ks + t4    ]);
                uint32_t b1 = __float_as_uint(Bs[buf][n0][ks + t4 + 4]);
#pragma unroll
                for (int mt = 0; mt < MT; mt++)
                    MMA_TF32(acc[mt][nt], af[mt][0], af[mt][1], af[mt][2], af[mt][3], b0, b1);
            }
        }
        if (has_next) {
            stash(buf ^ 1);
            __syncthreads();
            buf ^= 1;
        }
    }

    auto emit = [&](int gm, int gn, float v) {
        if (gm < M && gn < N) {
            v *= alpha;
            if (bias) v += bias[gn];
            if (relu) v = fmaxf(v, 0.f);
            if (addsrc) v += addsrc[(long long)gm * ldadd + gn];
            C[(long long)gm * ldc + gn] = v;
        }
    };
#pragma unroll
    for (int mt = 0; mt < MT; mt++) {
        int r0 = bm + wm + mt * 16 + g;
#pragma unroll
        for (int nt = 0; nt < NT; nt++) {
            int c0 = bn + wn + nt * 8 + t4 * 2;
            emit(r0,     c0,     acc[mt][nt][0]);
            emit(r0,     c0 + 1, acc[mt][nt][1]);
            emit(r0 + 8, c0,     acc[mt][nt][2]);
            emit(r0 + 8, c0 + 1, acc[mt][nt][3]);
        }
    }
}

// ---------------- fused flash attention (exact R5/R8) ----------------
#define SQS 68
#define STS 84

__global__ __launch_bounds__(128, 2)
void attn_kernel()
{
    extern __shared__ float sm[];
    float* sK  = sm;
    float* sV  = sK + 64 * SQS;
    float* sRK = sV + 64 * SQS;
    float* sT  = sRK + UW * SQS;
    float* sBW = sT + 64 * STS;
    float* sBR = sBW + 64;
    float* sC0 = sBR + 128;

    int it = blockIdx.x;
    int bh = blockIdx.y;
    int h = bh & 7, b = bh >> 3;
    int i0 = it * 64;
    int tid = threadIdx.x, lane = tid & 31, warp = tid >> 5;
    int g = lane >> 2, t4 = lane & 3;
    int wr = warp * 16;
    int nt0w = 6 - 2 * warp;

    const float* RKg = g_rkt + (long long)h * RKP * DH;
    const float* Vtg = g_vt + (long long)bh * DH * QQ;

    uint32_t afQ[8][4];
    {
        long long qb = (long long)(b * QQ + i0) * (3 * DD) + h * 64;
        const float* q0 = g_wh + qb + (long long)(wr + g) * (3 * DD);
        const float* q1 = g_wh + qb + (long long)(wr + g + 8) * (3 * DD);
#pragma unroll
        for (int ks = 0; ks < 8; ks++) {
            afQ[ks][0] = to_tf32u(q0[ks * 8 + t4]);
            afQ[ks][1] = to_tf32u(q1[ks * 8 + t4]);
            afQ[ks][2] = to_tf32u(q0[ks * 8 + t4 + 4]);
            afQ[ks][3] = to_tf32u(q1[ks * 8 + t4 + 4]);
        }
    }
    if (tid < 64) sC0[tid] = g_c0[bh * QQ + i0 + tid];

    float mrow[2] = {-1e30f, -1e30f};
    float lrow[2] = {0.f, 0.f};
    float msum[2] = {0.f, 0.f};
    float O[8][4];
#pragma unroll
    for (int nt = 0; nt < 8; nt++)
#pragma unroll
        for (int q = 0; q < 4; q++) O[nt][q] = 0.f;

    int njt = it + 9;
    for (int jt = 0; jt < njt; jt++) {
        int j0 = jt * 64;
        int mem = (jt < 8);
        int ub = j0 - i0 + 448;
        __syncthreads();
        {
            const float* rs = RKg + (long long)(ub + tid) * DH;
            float* rd = sRK + tid * SQS;
#pragma unroll
            for (int q = 0; q < 16; q++) {
                float4 v = *(const float4*)(rs + q * 4);
                rd[q*4+0] = to_tf32(v.x); rd[q*4+1] = to_tf32(v.y);
                rd[q*4+2] = to_tf32(v.z); rd[q*4+3] = to_tf32(v.w);
            }
        }
        if (!mem) {
            int r = tid >> 1, half = (tid & 1) * 32;
            const float* ksrc = g_wh + (long long)(b * QQ + j0 - MEML + r) * (3 * DD) + DD + h * 64 + half;
            float* kd = sK + r * SQS + half;
            const float* vsrc = Vtg + (long long)r * QQ + (j0 - MEML) + half;
            float* vd = sV + r * SQS + half;
#pragma unroll
            for (int q = 0; q < 8; q++) {
                float4 v = *(const float4*)(ksrc + q * 4);
                kd[q*4+0] = to_tf32(v.x); kd[q*4+1] = to_tf32(v.y);
                kd[q*4+2] = to_tf32(v.z); kd[q*4+3] = to_tf32(v.w);
                float4 w = *(const float4*)(vsrc + q * 4);
                vd[q*4+0] = to_tf32(w.x); vd[q*4+1] = to_tf32(w.y);
                vd[q*4+2] = to_tf32(w.z); vd[q*4+3] = to_tf32(w.w);
            }
            if (tid < 64) sBW[tid] = g_bwl[bh * QQ + (j0 - MEML) + tid];
        }
        sBR[tid] = g_br[h * RKP + ub + tid];
        __syncthreads();

        float ac[8][4];
        float tf[10][4];
#pragma unroll
        for (int nt = 0; nt < 8; nt++)
#pragma unroll
            for (int q = 0; q < 4; q++) ac[nt][q] = 0.f;
#pragma unroll
        for (int nt = 0; nt < 10; nt++)
#pragma unroll
            for (int q = 0; q < 4; q++) tf[nt][q] = 0.f;

#pragma unroll
        for (int ks = 0; ks < 8; ks++) {
            uint32_t a0 = afQ[ks][0], a1 = afQ[ks][1], a2 = afQ[ks][2], a3 = afQ[ks][3];
            if (!mem) {
#pragma unroll
                for (int nt = 0; nt < 8; nt++) {
                    uint32_t b0 = __float_as_uint(sK[(nt * 8 + g) * SQS + ks * 8 + t4    ]);
                    uint32_t b1 = __float_as_uint(sK[(nt * 8 + g) * SQS + ks * 8 + t4 + 4]);
                    MMA_TF32(ac[nt], a0, a1, a2, a3, b0, b1);
                }
            }
#pragma unroll
            for (int nt = 0; nt < 10; nt++) {
                int u = (nt0w + nt) * 8 + g;
                uint32_t b0 = __float_as_uint(sRK[u * SQS + ks * 8 + t4    ]);
                uint32_t b1 = __float_as_uint(sRK[u * SQS + ks * 8 + t4 + 4]);
                MMA_TF32(tf[nt], a0, a1, a2, a3, b0, b1);
            }
        }
        __syncthreads();

#pragma unroll
        for (int nt = 0; nt < 10; nt++) {
            int cr = nt * 8 + t4 * 2;
            sT[(wr + g    ) * STS + cr    ] = tf[nt][0];
            sT[(wr + g    ) * STS + cr + 1] = tf[nt][1];
            sT[(wr + g + 8) * STS + cr    ] = tf[nt][2];
            sT[(wr + g + 8) * STS + cr + 1] = tf[nt][3];
        }
        __syncwarp();

        int last = (jt == it + 8);
        float mt2[2] = {-1e30f, -1e30f};
#pragma unroll
        for (int nt = 0; nt < 8; nt++) {
            int jl0 = nt * 8 + t4 * 2;
#pragma unroll
            for (int r2 = 0; r2 < 2; r2++) {
                int il = wr + g + r2 * 8;
#pragma unroll
                for (int cc = 0; cc < 2; cc++) {
                    int jl = jl0 + cc;
                    int crel = jl - g - r2 * 8 + 15;
                    float base = mem ? sC0[il] : (ac[nt][r2*2+cc] + sBW[jl]);
                    float s = (base + sT[il * STS + crel] + sBR[jl - il + 63]) * 0.125f;
                    if (last && jl > il) s = -1e30f;
                    ac[nt][r2*2+cc] = s;
                    mt2[r2] = fmaxf(mt2[r2], s);
                }
            }
        }
#pragma unroll
        for (int r2 = 0; r2 < 2; r2++) {
            mt2[r2] = fmaxf(mt2[r2], __shfl_xor_sync(0xffffffffu, mt2[r2], 1));
            mt2[r2] = fmaxf(mt2[r2], __shfl_xor_sync(0xffffffffu, mt2[r2], 2));
        }
        float corr[2], ls[2] = {0.f, 0.f};
#pragma unroll
        for (int r2 = 0; r2 < 2; r2++) {
            float mnew = fmaxf(mrow[r2], mt2[r2]);
            corr[r2] = __expf(mrow[r2] - mnew);
            mrow[r2] = mnew;
        }
#pragma unroll
        for (int nt = 0; nt < 8; nt++)
#pragma unroll
            for (int r2 = 0; r2 < 2; r2++)
#pragma unroll
                for (int cc = 0; cc < 2; cc++) {
                    float e = __expf(ac[nt][r2*2+cc] - mrow[r2]);
                    ac[nt][r2*2+cc] = e;
                    ls[r2] += e;
                }
#pragma unroll
        for (int r2 = 0; r2 < 2; r2++) {
            ls[r2] += __shfl_xor_sync(0xffffffffu, ls[r2], 1);
            ls[r2] += __shfl_xor_sync(0xffffffffu, ls[r2], 2);
            lrow[r2] = lrow[r2] * corr[r2] + ls[r2];
            msum[r2] *= corr[r2];
            if (mem) msum[r2] += ls[r2];
        }
#pragma unroll
        for (int nt = 0; nt < 8; nt++)
#pragma unroll
            for (int q = 0; q < 4; q++) O[nt][q] *= corr[q >> 1];

        if (!mem) {
#pragma unroll
            for (int nt = 0; nt < 8; nt++) {
                int c = nt * 8 + t4 * 2;
                sRK[(wr + g    ) * SQS + c    ] = to_tf32(ac[nt][0]);
                sRK[(wr + g    ) * SQS + c + 1] = to_tf32(ac[nt][1]);
                sRK[(wr + g + 8) * SQS + c    ] = to_tf32(ac[nt][2]);
                sRK[(wr + g + 8) * SQS + c + 1] = to_tf32(ac[nt][3]);
            }
            __syncwarp();
#pragma unroll
            for (int ks = 0; ks < 8; ks++) {
                uint32_t a0 = __float_as_uint(sRK[(wr + g    ) * SQS + ks * 8 + t4    ]);
                uint32_t a1 = __float_as_uint(sRK[(wr + g + 8) * SQS + ks * 8 + t4    ]);
                uint32_t a2 = __float_as_uint(sRK[(wr + g    ) * SQS + ks * 8 + t4 + 4]);
                uint32_t a3 = __float_as_uint(sRK[(wr + g + 8) * SQS + ks * 8 + t4 + 4]);
#pragma unroll
                for (int nt = 0; nt < 8; nt++) {
                    uint32_t b0 = __float_as_uint(sV[(nt * 8 + g) * SQS + ks * 8 + t4    ]);
                    uint32_t b1 = __float_as_uint(sV[(nt * 8 + g) * SQS + ks * 8 + t4 + 4]);
                    MMA_TF32(O[nt], a0, a1, a2, a3, b0, b1);
                }
            }
        }
    }

    float inv0 = 1.f / lrow[0], inv1 = 1.f / lrow[1];
    const float* vm = g_whmem + 2 * DD + h * 64;
    long long r0 = (long long)(b * QQ + i0 + wr + g) * DD + h * 64;
    long long r1 = (long long)(b * QQ + i0 + wr + g + 8) * DD + h * 64;
#pragma unroll
    for (int nt = 0; nt < 8; nt++) {
        int c = nt * 8 + t4 * 2;
        float v0 = vm[c], v1 = vm[c + 1];
        g_attn[r0 + c]     = (O[nt][0] + msum[0] * v0) * inv0;
        g_attn[r0 + c + 1] = (O[nt][1] + msum[0] * v1) * inv0;
        g_attn[r1 + c]     = (O[nt][2] + msum[1] * v0) * inv1;
        g_attn[r1 + c + 1] = (O[nt][3] + msum[1] * v1) * inv1;
    }
}

// ---------------- layernorm (vectorized, 2 rows/block) ----------------
__global__ void ln_kernel(const float* __restrict__ x, float* __restrict__ y,
                          const float* __restrict__ g, const float* __restrict__ b)
{
    int tid = threadIdx.x;
    int half = tid >> 7;
    int t = tid & 127;
    int row = blockIdx.x * 2 + half;
    const float* xr = x + (long long)row * DD;
    float* yr = y + (long long)row * DD;
    float4 v = *(const float4*)(xr + t * 4);
    float s = v.x + v.y + v.z + v.w;
    float s2 = v.x*v.x + v.y*v.y + v.z*v.z + v.w*v.w;
    __shared__ float sh[2][8];
    __shared__ float stats[2][2];
#pragma unroll
    for (int o = 16; o > 0; o >>= 1) {
        s  += __shfl_xor_sync(0xffffffffu, s,  o);
        s2 += __shfl_xor_sync(0xffffffffu, s2, o);
    }
    int w4 = (tid >> 5) & 3;
    if ((tid & 31) == 0) { sh[half][w4] = s; sh[half][w4 + 4] = s2; }
    __syncthreads();
    if (t == 0) {
        float S = sh[half][0] + sh[half][1] + sh[half][2] + sh[half][3];
        float S2 = sh[half][4] + sh[half][5] + sh[half][6] + sh[half][7];
        float mu = S / DD;
        float var = S2 / DD - mu * mu;
        stats[half][0] = mu;
        stats[half][1] = rsqrtf(var + 1e-3f);
    }
    __syncthreads();
    float mu = stats[half][0], rs = stats[half][1];
    float4 gv = *(const float4*)(g + t * 4);
    float4 bv = *(const float4*)(b + t * 4);
    float4 o;
    o.x = (v.x - mu) * rs * gv.x + bv.x;
    o.y = (v.y - mu) * rs * gv.y + bv.y;
    o.z = (v.z - mu) * rs * gv.z + bv.z;
    o.w = (v.w - mu) * rs * gv.w + bv.w;
    *(float4*)(yr + t * 4) = o;
}

__global__ void whmem_kernel(const float* __restrict__ qkvw, const float* __restrict__ lnb)
{
    int n = blockIdx.x * blockDim.x + threadIdx.x;
    if (n >= 3 * DD) return;
    const float* wr = qkvw + (long long)n * DD;
    float s = 0.f;
    for (int c = 0; c < DD; c++) s += lnb[c] * wr[c];
    g_whmem[n] = s;
}

__global__ void posemb_kernel()
{
    int idx = blockIdx.x * blockDim.x + threadIdx.x;
    if (idx >= KKT * DD) return;
    int p = idx / DD, c = idx % DD;
    float pos = (float)(KKT - 1 - p);
    int k = (c < 256) ? c : (c - 256);
    float invf = powf(10000.0f, -((float)(2 * k)) / 512.0f);
    float a = pos * invf;
    g_posemb[idx] = (c < 256) ? sinf(a) : cosf(a);
}

__global__ void gather_kernel(const int* __restrict__ ids, const float* __restrict__ emb)
{
    int idx = blockIdx.x * blockDim.x + threadIdx.x;
    if (idx >= BB * QQ * DD) return;
    int m = idx / DD, c = idx % DD;
    g_gath[idx] = emb[(long long)ids[m] * DD + c];
}

// ---------------- merged attention-prep kernel (regions A-D) ----------------
#define PREP_A 2304
#define PREP_B (PREP_A + 4096)
#define PREP_C (PREP_B + 36)
#define PREP_D (PREP_C + 8192)

__global__ void prep_kernel(const float* __restrict__ rwb, const float* __restrict__ rrb)
{
    int blk = blockIdx.x;
    int tid = threadIdx.x;
    if (blk < PREP_A) {
        int idx = blk * 256 + tid;
        int d = idx & 63;
        int p = (idx >> 6) % RKP;
        int h = idx / (RKP * DH);
        g_rkt[idx] = (p < KKT) ? g_rk[(long long)p * DD + h * 64 + d] : 0.f;
    } else if (blk < PREP_B) {
        int idx = (blk - PREP_A) * 256 + tid;
        int jq = idx & 511;
        int d  = (idx >> 9) & 63;
        int bh = idx >> 15;
        int b = bh >> 3, h = bh & 7;
        g_vt[idx] = g_wh[(long long)(b * QQ + jq) * (3 * DD) + 2 * DD + h * 64 + d];
    } else if (blk < PREP_C) {
        int idx = (blk - PREP_B) * 256 + tid;
        if (idx >= HH * RKP) return;
        int h = idx / RKP, u = idx % RKP;
        float s = 0.f;
        if (u < KKT) {
            const float* rr = g_rk + (long long)u * DD + h * 64;
            const float* w = rrb + h * DH;
#pragma unroll
            for (int d = 0; d < DH; d++) s += w[d] * rr[d];
        }
        g_br[idx] = s;
    } else {
        int unit = tid >> 6;
        int t = tid & 63;
        int row = (blk - PREP_C) * 4 + unit;
        int kind = row >> 14;
        int r = row & 16383;
        int bh = r >> 9, iq = r & 511;
        int h = bh & 7, b = bh >> 3;
        long long base = (long long)(b * QQ + iq) * (3 * DD) + h * 64;
        float v;
        if (kind == 0) {
            v = (g_wh[base + t] + rwb[h * 64 + t]) * g_whmem[DD + h * 64 + t];
        } else {
            v = rwb[h * 64 + t] * g_wh[base + DD + t];
        }
#pragma unroll
        for (int o = 16; o > 0; o >>= 1) v += __shfl_xor_sync(0xffffffffu, v, o);
        __shared__ float sh[8];
        if ((t & 31) == 0) sh[unit * 2 + (t >> 5)] = v;
        __syncthreads();
        if (t == 0) {
            float s = sh[unit * 2] + sh[unit * 2 + 1];
            if (kind == 0) g_c0[r] = s; else g_bwl[r] = s;
        }
    }
}

// ---------------- host ----------------
static void gemm(const float* A, const float* B, float* C,
                 int M, int N, int K, int ldc,
                 const float* add, int ldadd, const float* bias,
                 float alpha, int relu)
{
    if (N > 512) {
        // wide (QKV, FF1): grid already > 148 at 128x128; reuse wins
        dim3 grid((N + 127) / 128, (M + 127) / 128);
        gemm_t<128, 128, 256, 2, 2, 8><<<grid, 256>>>(A, B, C, M, N, K, ldc,
                                                      add, ldadd, bias, alpha, relu);
    } else {
        // narrow: 64x64 tiles, 128 thr, up to 5 blocks/SM
        dim3 grid((N + 63) / 64, (M + 63) / 64);
        gemm_t<64, 64, 128, 5, 2, 4><<<grid, 128>>>(A, B, C, M, N, K, ldc,
                                                    add, ldadd, bias, alpha, relu);
    }
}

extern "C" void kernel_launch(void* const* d_in, const int* in_sizes, int n_in,
                              void* d_out, int out_size)
{
    const int*   ids      = (const int*)d_in[0];
    const float* emb      = (const float*)d_in[1];
    const float* emb_proj = (const float*)d_in[2];
    const float* rwb      = (const float*)d_in[3];
    const float* rrb      = (const float*)d_in[4];
    const float* qkv_w    = (const float*)d_in[5];
    const float* o_w      = (const float*)d_in[6];
    const float* rnet_w   = (const float*)d_in[7];
    const float* ln1g     = (const float*)d_in[8];
    const float* ln1b     = (const float*)d_in[9];
    const float* ff1w     = (const float*)d_in[10];
    const float* ff1b     = (const float*)d_in[11];
    const float* ff2w     = (const float*)d_in[12];
    const float* ff2b     = (const float*)d_in[13];
    const float* ln2g     = (const float*)d_in[14];
    const float* ln2b     = (const float*)d_in[15];
    const float* headw    = (const float*)d_in[16];
    const float* headb    = (const float*)d_in[17];
    float* out = (float*)d_out;

    float *p_h, *p_norm, *p_wh, *p_posemb, *p_rk, *p_attn, *p_ff, *p_gath;
    void* tmp;
#define SYM(v, s) cudaGetSymbolAddress(&tmp, s); v = (float*)tmp;
    SYM(p_h, g_h) SYM(p_norm, g_norm) SYM(p_wh, g_wh) SYM(p_posemb, g_posemb)
    SYM(p_rk, g_rk) SYM(p_attn, g_attn) SYM(p_ff, g_ff) SYM(p_gath, g_gath)
#undef SYM

    const int ATTN_SMEM = (2 * 64 * SQS + UW * SQS + 64 * STS + 64 + 128 + 64) * 4;
    cudaFuncSetAttribute(attn_kernel, cudaFuncAttributeMaxDynamicSharedMemorySize, ATTN_SMEM);

    const int MQ = BB * QQ;

    gather_kernel<<<(MQ * DD + 255) / 256, 256>>>(ids, emb);
    posemb_kernel<<<(KKT * DD + 255) / 256, 256>>>();
    gemm(p_gath, emb_proj, p_h, MQ, DD, DD, DD,
         nullptr, 0, nullptr, sqrtf((float)DD), 0);

    for (int l = 0; l < NL; l++) {
        const float* qkvw_l = qkv_w + (long long)l * 3 * DD * DD;
        const float* ow_l   = o_w   + (long long)l * DD * DD;
        const float* rnw_l  = rnet_w+ (long long)l * DD * DD;
        const float* f1w_l  = ff1w  + (long long)l * DFF * DD;
        const float* f1b_l  = ff1b  + (long long)l * DFF;
        const float* f2w_l  = ff2w  + (long long)l * DD * DFF;
        const float* f2b_l  = ff2b  + (long long)l * DD;

        ln_kernel<<<MQ / 2, 256>>>(p_h, p_norm, ln1g + l * DD, ln1b + l * DD);
        whmem_kernel<<<12, 128>>>(qkvw_l, ln1b + l * DD);
        gemm(p_norm, qkvw_l, p_wh, MQ, 3 * DD, DD, 3 * DD,
             nullptr, 0, nullptr, 1.f, 0);

        gemm(p_posemb, rnw_l, p_rk, KKT, DD, DD, DD,
             nullptr, 0, nullptr, 1.f, 0);

        prep_kernel<<<PREP_D, 256>>>(rwb, rrb);

        attn_kernel<<<dim3(QQ / 64, BB * HH), 128, ATTN_SMEM>>>();

        gemm(p_attn, ow_l, p_h, MQ, DD, DD, DD,
             p_h, DD, nullptr, 1.f, 0);

        ln_kernel<<<MQ / 2, 256>>>(p_h, p_norm, ln2g + l * DD, ln2b + l * DD);
        gemm(p_norm, f1w_l, p_ff, MQ, DFF, DD, DFF,
             nullptr, 0, f1b_l, 1.f, 1);
        gemm(p_ff, f2w_l, p_h, MQ, DD, DFF, DD,
             p_h, DD, f2b_l, 1.f, 0);
    }

    gemm(p_h, headw, out, MQ, NV, DD, NV,
         nullptr, 0, headb, 1.f, 0);
}

// round 15
// speedup vs baseline: 1.2302x; 1.1768x over previous
#include <cuda_runtime.h>
#include <math.h>
#include <stdint.h>

#define BB   4
#define QQ   512
#define KKT  1024
#define DD   512
#define HH   8
#define DH   64
#define DFF  2048
#define NL   12
#define NV   332
#define MEML 512
#define UW   128
#define RKP  (KKT + UW)

// ---------------- scratch ----------------
__device__ float g_h[BB*QQ*DD];
__device__ float g_norm[BB*QQ*DD];
__device__ float g_wh[BB*QQ*3*DD];
__device__ float g_whmem_all[NL*3*DD];
__device__ float g_posemb[KKT*DD];
__device__ float g_rkall[KKT*NL*DD];          // rk for all layers, [p][l*512+n]
__device__ float g_rkt_all[(long)NL*HH*RKP*DH];
__device__ float g_br_all[NL*HH*RKP];
__device__ float g_vt[BB*HH*DH*QQ];
__device__ float g_c0[BB*HH*QQ];
__device__ float g_bwl[BB*HH*QQ];
__device__ float g_attn[BB*QQ*DD];
__device__ float g_ff[BB*QQ*DFF];
__device__ float g_gath[BB*QQ*DD];

__device__ __forceinline__ float to_tf32(float x) {
    uint32_t u;
    asm("cvt.rna.tf32.f32 %0, %1;" : "=r"(u) : "f"(x));
    return __uint_as_float(u);
}
__device__ __forceinline__ uint32_t to_tf32u(float x) {
    uint32_t u;
    asm("cvt.rna.tf32.f32 %0, %1;" : "=r"(u) : "f"(x));
    return u;
}

#define MMA_TF32(acc, a0,a1,a2,a3, b0,b1) \
    asm volatile("mma.sync.aligned.m16n8k8.row.col.f32.tf32.tf32.f32 " \
                 "{%0,%1,%2,%3}, {%4,%5,%6,%7}, {%8,%9}, {%0,%1,%2,%3};" \
                 : "+f"(acc[0]), "+f"(acc[1]), "+f"(acc[2]), "+f"(acc[3]) \
                 : "r"(a0), "r"(a1), "r"(a2), "r"(a3), "r"(b0), "r"(b1))

// ---------------- templated tf32 GEMM (exact R14) ----------------
template<int BMT, int BNT, int TT, int MB, int MT, int NT>
__global__ __launch_bounds__(TT, MB)
void gemm_t(const float* __restrict__ A, const float* __restrict__ B,
            float* __restrict__ C,
            int M, int N, int Kd, int ldc,
            const float* __restrict__ addsrc, int ldadd,
            const float* __restrict__ bias,
            float alpha, int relu)
{
    constexpr int R4 = TT / 4;
    constexpr int IA = (BMT + R4 - 1) / R4;
    constexpr int IB = (BNT + R4 - 1) / R4;
    constexpr int NW_N = BNT / (NT * 8);

    __shared__ float As[2][BMT][20];
    __shared__ float Bs[2][BNT][20];

    int bm = blockIdx.y * BMT, bn = blockIdx.x * BNT;
    int tid  = threadIdx.x;
    int lane = tid & 31, warp = tid >> 5;
    int g  = lane >> 2, t4 = lane & 3;
    int wm = (warp / NW_N) * (MT * 16);
    int wn = (warp % NW_N) * (NT * 8);

    int lrow = tid >> 2;
    int lkq  = (tid & 3) * 4;

    float acc[MT][NT][4];
#pragma unroll
    for (int mt = 0; mt < MT; mt++)
#pragma unroll
        for (int nt = 0; nt < NT; nt++)
#pragma unroll
            for (int q = 0; q < 4; q++) acc[mt][nt][q] = 0.f;

    float4 pa[IA], pb[IB];

    auto ldgA = [&](int k0, int it) -> float4 {
        int r = lrow + it * R4;
        int gm = bm + r;
        if (r < BMT && gm < M) return *(const float4*)&A[(long long)gm * Kd + k0 + lkq];
        return make_float4(0.f, 0.f, 0.f, 0.f);
    };
    auto ldgB = [&](int k0, int it) -> float4 {
        int r = lrow + it * R4;
        int gn = bn + r;
        if (r < BNT && gn < N) return *(const float4*)&B[(long long)gn * Kd + k0 + lkq];
        return make_float4(0.f, 0.f, 0.f, 0.f);
    };
    auto stash = [&](int buf) {
#pragma unroll
        for (int it = 0; it < IA; it++) {
            int r = lrow + it * R4;
            if (r < BMT) {
                float4 ta = make_float4(to_tf32(pa[it].x), to_tf32(pa[it].y),
                                        to_tf32(pa[it].z), to_tf32(pa[it].w));
                *(float4*)&As[buf][r][lkq] = ta;
            }
        }
#pragma unroll
        for (int it = 0; it < IB; it++) {
            int r = lrow + it * R4;
            if (r < BNT) {
                float4 tb = make_float4(to_tf32(pb[it].x), to_tf32(pb[it].y),
                                        to_tf32(pb[it].z), to_tf32(pb[it].w));
                *(float4*)&Bs[buf][r][lkq] = tb;
            }
        }
    };

    int nk = Kd >> 4;
#pragma unroll
    for (int it = 0; it < IA; it++) pa[it] = ldgA(0, it);
#pragma unroll
    for (int it = 0; it < IB; it++) pb[it] = ldgB(0, it);
    stash(0);
    __syncthreads();

    int buf = 0;
    for (int t = 0; t < nk; t++) {
        int has_next = (t + 1 < nk);
        if (has_next) {
            int k0 = (t + 1) << 4;
#pragma unroll
            for (int it = 0; it < IA; it++) pa[it] = ldgA(k0, it);
#pragma unroll
            for (int it = 0; it < IB; it++) pb[it] = ldgB(k0, it);
        }
#pragma unroll
        for (int ks = 0; ks < 16; ks += 8) {
            uint32_t af[MT][4];
#pragma unroll
            for (int mt = 0; mt < MT; mt++) {
                int m0 = wm + mt * 16 + g;
                af[mt][0] = __float_as_uint(As[buf][m0    ][ks + t4    ]);
                af[mt][1] = __float_as_uint(As[buf][m0 + 8][ks + t4    ]);
                af[mt][2] = __float_as_uint(As[buf][m0    ][ks + t4 + 4]);
                af[mt][3] = __float_as_uint(As[buf][m0 + 8][ks + t4 + 4]);
            }
#pragma unroll
            for (int nt = 0; nt < NT; nt++) {
                int n0 = wn + nt * 8 + g;
                uint32_t b0 = __float_as_uint(Bs[buf][n0][ks + t4    ]);
                uint32_t b1 = __float_as_uint(Bs[buf][n0][ks + t4 + 4]);
#pragma unroll
                for (int mt = 0; mt < MT; mt++)
                    MMA_TF32(acc[mt][nt], af[mt][0], af[mt][1], af[mt][2], af[mt][3], b0, b1);
            }
        }
        if (has_next) {
            stash(buf ^ 1);
            __syncthreads();
            buf ^= 1;
        }
    }

    auto emit = [&](int gm, int gn, float v) {
        if (gm < M && gn < N) {
            v *= alpha;
            if (bias) v += bias[gn];
            if (relu) v = fmaxf(v, 0.f);
            if (addsrc) v += addsrc[(long long)gm * ldadd + gn];
            C[(long long)gm * ldc + gn] = v;
        }
    };
#pragma unroll
    for (int mt = 0; mt < MT; mt++) {
        int r0 = bm + wm + mt * 16 + g;
#pragma unroll
        for (int nt = 0; nt < NT; nt++) {
            int c0 = bn + wn + nt * 8 + t4 * 2;
            emit(r0,     c0,     acc[mt][nt][0]);
            emit(r0,     c0 + 1, acc[mt][nt][1]);
            emit(r0 + 8, c0,     acc[mt][nt][2]);
            emit(r0 + 8, c0 + 1, acc[mt][nt][3]);
        }
    }
}

// ---------------- fused flash attention (R14 + layer index) ----------------
#define SQS 68
#define STS 84

__global__ __launch_bounds__(128, 2)
void attn_kernel(int l)
{
    extern __shared__ float sm[];
    float* sK  = sm;
    float* sV  = sK + 64 * SQS;
    float* sRK = sV + 64 * SQS;
    float* sT  = sRK + UW * SQS;
    float* sBW = sT + 64 * STS;
    float* sBR = sBW + 64;
    float* sC0 = sBR + 128;

    int it = blockIdx.x;
    int bh = blockIdx.y;
    int h = bh & 7, b = bh >> 3;
    int i0 = it * 64;
    int tid = threadIdx.x, lane = tid & 31, warp = tid >> 5;
    int g = lane >> 2, t4 = lane & 3;
    int wr = warp * 16;
    int nt0w = 6 - 2 * warp;

    const float* RKg = g_rkt_all + ((long long)l * HH + h) * RKP * DH;
    const float* BRg = g_br_all + (l * HH + h) * RKP;
    const float* Vtg = g_vt + (long long)bh * DH * QQ;

    uint32_t afQ[8][4];
    {
        long long qb = (long long)(b * QQ + i0) * (3 * DD) + h * 64;
        const float* q0 = g_wh + qb + (long long)(wr + g) * (3 * DD);
        const float* q1 = g_wh + qb + (long long)(wr + g + 8) * (3 * DD);
#pragma unroll
        for (int ks = 0; ks < 8; ks++) {
            afQ[ks][0] = to_tf32u(q0[ks * 8 + t4]);
            afQ[ks][1] = to_tf32u(q1[ks * 8 + t4]);
            afQ[ks][2] = to_tf32u(q0[ks * 8 + t4 + 4]);
            afQ[ks][3] = to_tf32u(q1[ks * 8 + t4 + 4]);
        }
    }
    if (tid < 64) sC0[tid] = g_c0[bh * QQ + i0 + tid];

    float mrow[2] = {-1e30f, -1e30f};
    float lrow[2] = {0.f, 0.f};
    float msum[2] = {0.f, 0.f};
    float O[8][4];
#pragma unroll
    for (int nt = 0; nt < 8; nt++)
#pragma unroll
        for (int q = 0; q < 4; q++) O[nt][q] = 0.f;

    int njt = it + 9;
    for (int jt = 0; jt < njt; jt++) {
        int j0 = jt * 64;
        int mem = (jt < 8);
        int ub = j0 - i0 + 448;
        __syncthreads();
        {
            const float* rs = RKg + (long long)(ub + tid) * DH;
            float* rd = sRK + tid * SQS;
#pragma unroll
            for (int q = 0; q < 16; q++) {
                float4 v = *(const float4*)(rs + q * 4);
                rd[q*4+0] = to_tf32(v.x); rd[q*4+1] = to_tf32(v.y);
                rd[q*4+2] = to_tf32(v.z); rd[q*4+3] = to_tf32(v.w);
            }
        }
        if (!mem) {
            int r = tid >> 1, half = (tid & 1) * 32;
            const float* ksrc = g_wh + (long long)(b * QQ + j0 - MEML + r) * (3 * DD) + DD + h * 64 + half;
            float* kd = sK + r * SQS + half;
            const float* vsrc = Vtg + (long long)r * QQ + (j0 - MEML) + half;
            float* vd = sV + r * SQS + half;
#pragma unroll
            for (int q = 0; q < 8; q++) {
                float4 v = *(const float4*)(ksrc + q * 4);
                kd[q*4+0] = to_tf32(v.x); kd[q*4+1] = to_tf32(v.y);
                kd[q*4+2] = to_tf32(v.z); kd[q*4+3] = to_tf32(v.w);
                float4 w = *(const float4*)(vsrc + q * 4);
                vd[q*4+0] = to_tf32(w.x); vd[q*4+1] = to_tf32(w.y);
                vd[q*4+2] = to_tf32(w.z); vd[q*4+3] = to_tf32(w.w);
            }
            if (tid < 64) sBW[tid] = g_bwl[bh * QQ + (j0 - MEML) + tid];
        }
        sBR[tid] = BRg[ub + tid];
        __syncthreads();

        float ac[8][4];
        float tf[10][4];
#pragma unroll
        for (int nt = 0; nt < 8; nt++)
#pragma unroll
            for (int q = 0; q < 4; q++) ac[nt][q] = 0.f;
#pragma unroll
        for (int nt = 0; nt < 10; nt++)
#pragma unroll
            for (int q = 0; q < 4; q++) tf[nt][q] = 0.f;

#pragma unroll
        for (int ks = 0; ks < 8; ks++) {
            uint32_t a0 = afQ[ks][0], a1 = afQ[ks][1], a2 = afQ[ks][2], a3 = afQ[ks][3];
            if (!mem) {
#pragma unroll
                for (int nt = 0; nt < 8; nt++) {
                    uint32_t b0 = __float_as_uint(sK[(nt * 8 + g) * SQS + ks * 8 + t4    ]);
                    uint32_t b1 = __float_as_uint(sK[(nt * 8 + g) * SQS + ks * 8 + t4 + 4]);
                    MMA_TF32(ac[nt], a0, a1, a2, a3, b0, b1);
                }
            }
#pragma unroll
            for (int nt = 0; nt < 10; nt++) {
                int u = (nt0w + nt) * 8 + g;
                uint32_t b0 = __float_as_uint(sRK[u * SQS + ks * 8 + t4    ]);
                uint32_t b1 = __float_as_uint(sRK[u * SQS + ks * 8 + t4 + 4]);
                MMA_TF32(tf[nt], a0, a1, a2, a3, b0, b1);
            }
        }
        __syncthreads();

#pragma unroll
        for (int nt = 0; nt < 10; nt++) {
            int cr = nt * 8 + t4 * 2;
            sT[(wr + g    ) * STS + cr    ] = tf[nt][0];
            sT[(wr + g    ) * STS + cr + 1] = tf[nt][1];
            sT[(wr + g + 8) * STS + cr    ] = tf[nt][2];
            sT[(wr + g + 8) * STS + cr + 1] = tf[nt][3];
        }
        __syncwarp();

        int last = (jt == it + 8);
        float mt2[2] = {-1e30f, -1e30f};
#pragma unroll
        for (int nt = 0; nt < 8; nt++) {
            int jl0 = nt * 8 + t4 * 2;
#pragma unroll
            for (int r2 = 0; r2 < 2; r2++) {
                int il = wr + g + r2 * 8;
#pragma unroll
                for (int cc = 0; cc < 2; cc++) {
                    int jl = jl0 + cc;
                    int crel = jl - g - r2 * 8 + 15;
                    float base = mem ? sC0[il] : (ac[nt][r2*2+cc] + sBW[jl]);
                    float s = (base + sT[il * STS + crel] + sBR[jl - il + 63]) * 0.125f;
                    if (last && jl > il) s = -1e30f;
                    ac[nt][r2*2+cc] = s;
                    mt2[r2] = fmaxf(mt2[r2], s);
                }
            }
        }
#pragma unroll
        for (int r2 = 0; r2 < 2; r2++) {
            mt2[r2] = fmaxf(mt2[r2], __shfl_xor_sync(0xffffffffu, mt2[r2], 1));
            mt2[r2] = fmaxf(mt2[r2], __shfl_xor_sync(0xffffffffu, mt2[r2], 2));
        }
        float corr[2], ls[2] = {0.f, 0.f};
#pragma unroll
        for (int r2 = 0; r2 < 2; r2++) {
            float mnew = fmaxf(mrow[r2], mt2[r2]);
            corr[r2] = __expf(mrow[r2] - mnew);
            mrow[r2] = mnew;
        }
#pragma unroll
        for (int nt = 0; nt < 8; nt++)
#pragma unroll
            for (int r2 = 0; r2 < 2; r2++)
#pragma unroll
                for (int cc = 0; cc < 2; cc++) {
                    float e = __expf(ac[nt][r2*2+cc] - mrow[r2]);
                    ac[nt][r2*2+cc] = e;
                    ls[r2] += e;
                }
#pragma unroll
        for (int r2 = 0; r2 < 2; r2++) {
            ls[r2] += __shfl_xor_sync(0xffffffffu, ls[r2], 1);
            ls[r2] += __shfl_xor_sync(0xffffffffu, ls[r2], 2);
            lrow[r2] = lrow[r2] * corr[r2] + ls[r2];
            msum[r2] *= corr[r2];
            if (mem) msum[r2] += ls[r2];
        }
#pragma unroll
        for (int nt = 0; nt < 8; nt++)
#pragma unroll
            for (int q = 0; q < 4; q++) O[nt][q] *= corr[q >> 1];

        if (!mem) {
#pragma unroll
            for (int nt = 0; nt < 8; nt++) {
                int c = nt * 8 + t4 * 2;
                sRK[(wr + g    ) * SQS + c    ] = to_tf32(ac[nt][0]);
                sRK[(wr + g    ) * SQS + c + 1] = to_tf32(ac[nt][1]);
                sRK[(wr + g + 8) * SQS + c    ] = to_tf32(ac[nt][2]);
                sRK[(wr + g + 8) * SQS + c + 1] = to_tf32(ac[nt][3]);
            }
            __syncwarp();
#pragma unroll
            for (int ks = 0; ks < 8; ks++) {
                uint32_t a0 = __float_as_uint(sRK[(wr + g    ) * SQS + ks * 8 + t4    ]);
                uint32_t a1 = __float_as_uint(sRK[(wr + g + 8) * SQS + ks * 8 + t4    ]);
                uint32_t a2 = __float_as_uint(sRK[(wr + g    ) * SQS + ks * 8 + t4 + 4]);
                uint32_t a3 = __float_as_uint(sRK[(wr + g + 8) * SQS + ks * 8 + t4 + 4]);
#pragma unroll
                for (int nt = 0; nt < 8; nt++) {
                    uint32_t b0 = __float_as_uint(sV[(nt * 8 + g) * SQS + ks * 8 + t4    ]);
                    uint32_t b1 = __float_as_uint(sV[(nt * 8 + g) * SQS + ks * 8 + t4 + 4]);
                    MMA_TF32(O[nt], a0, a1, a2, a3, b0, b1);
                }
            }
        }
    }

    float inv0 = 1.f / lrow[0], inv1 = 1.f / lrow[1];
    const float* vm = g_whmem_all + l * 3 * DD + 2 * DD + h * 64;
    long long r0 = (long long)(b * QQ + i0 + wr + g) * DD + h * 64;
    long long r1 = (long long)(b * QQ + i0 + wr + g + 8) * DD + h * 64;
#pragma unroll
    for (int nt = 0; nt < 8; nt++) {
        int c = nt * 8 + t4 * 2;
        float v0 = vm[c], v1 = vm[c + 1];
        g_attn[r0 + c]     = (O[nt][0] + msum[0] * v0) * inv0;
        g_attn[r0 + c + 1] = (O[nt][1] + msum[0] * v1) * inv0;
        g_attn[r1 + c]     = (O[nt][2] + msum[1] * v0) * inv1;
        g_attn[r1 + c + 1] = (O[nt][3] + msum[1] * v1) * inv1;
    }
}

// ---------------- layernorm (vectorized, 2 rows/block) ----------------
__global__ void ln_kernel(const float* __restrict__ x, float* __restrict__ y,
                          const float* __restrict__ g, const float* __restrict__ b)
{
    int tid = threadIdx.x;
    int half = tid >> 7;
    int t = tid & 127;
    int row = blockIdx.x * 2 + half;
    const float* xr = x + (long long)row * DD;
    float* yr = y + (long long)row * DD;
    float4 v = *(const float4*)(xr + t * 4);
    float s = v.x + v.y + v.z + v.w;
    float s2 = v.x*v.x + v.y*v.y + v.z*v.z + v.w*v.w;
    __shared__ float sh[2][8];
    __shared__ float stats[2][2];
#pragma unroll
    for (int o = 16; o > 0; o >>= 1) {
        s  += __shfl_xor_sync(0xffffffffu, s,  o);
        s2 += __shfl_xor_sync(0xffffffffu, s2, o);
    }
    int w4 = (tid >> 5) & 3;
    if ((tid & 31) == 0) { sh[half][w4] = s; sh[half][w4 + 4] = s2; }
    __syncthreads();
    if (t == 0) {
        float S = sh[half][0] + sh[half][1] + sh[half][2] + sh[half][3];
        float S2 = sh[half][4] + sh[half][5] + sh[half][6] + sh[half][7];
        float mu = S / DD;
        float var = S2 / DD - mu * mu;
        stats[half][0] = mu;
        stats[half][1] = rsqrtf(var + 1e-3f);
    }
    __syncthreads();
    float mu = stats[half][0], rs = stats[half][1];
    float4 gv = *(const float4*)(g + t * 4);
    float4 bv = *(const float4*)(b + t * 4);
    float4 o;
    o.x = (v.x - mu) * rs * gv.x + bv.x;
    o.y = (v.y - mu) * rs * gv.y + bv.y;
    o.z = (v.z - mu) * rs * gv.z + bv.z;
    o.w = (v.w - mu) * rs * gv.w + bv.w;
    *(float4*)(yr + t * 4) = o;
}

// whmem for ALL layers: one warp per output (l, n)
__global__ void whmem_all_kernel(const float* __restrict__ qkvw, const float* __restrict__ ln1b)
{
    int gw = (blockIdx.x * 256 + threadIdx.x) >> 5;
    int lane = threadIdx.x & 31;
    if (gw >= NL * 3 * DD) return;
    int l = gw / (3 * DD), n = gw % (3 * DD);
    const float* wr = qkvw + ((long long)l * 3 * DD + n) * DD;
    const float* lb = ln1b + l * DD;
    float s = 0.f;
#pragma unroll
    for (int i = 0; i < 16; i++) s += lb[lane + i * 32] * wr[lane + i * 32];
#pragma unroll
    for (int o = 16; o > 0; o >>= 1) s += __shfl_xor_sync(0xffffffffu, s, o);
    if (lane == 0) g_whmem_all[gw] = s;
}

__global__ void posemb_kernel()
{
    int idx = blockIdx.x * blockDim.x + threadIdx.x;
    if (idx >= KKT * DD) return;
    int p = idx / DD, c = idx % DD;
    float pos = (float)(KKT - 1 - p);
    int k = (c < 256) ? c : (c - 256);
    float invf = powf(10000.0f, -((float)(2 * k)) / 512.0f);
    float a = pos * invf;
    g_posemb[idx] = (c < 256) ? sinf(a) : cosf(a);
}

__global__ void gather_kernel(const int* __restrict__ ids, const float* __restrict__ emb)
{
    int idx = blockIdx.x * blockDim.x + threadIdx.x;
    if (idx >= BB * QQ * DD) return;
    int m = idx / DD, c = idx % DD;
    g_gath[idx] = emb[(long long)ids[m] * DD + c];
}

// ---- batched rk pack + br for all layers (runs once) ----
// region A (27648 blocks): g_rkt_all[l][h][p][d] from g_rkall (0-padded)
// region B (432 blocks):   g_br_all[l][h][u]
#define PKA 27648
#define PKB (PKA + 432)

__global__ void packrkbr_all_kernel(const float* __restrict__ rrb)
{
    long long blk = blockIdx.x;
    int tid = threadIdx.x;
    if (blk < PKA) {
        long long idx = blk * 256 + tid;
        int d = (int)(idx & 63);
        int p = (int)((idx >> 6) % RKP);
        int lh = (int)(idx / ((long long)RKP * DH));
        int l = lh >> 3, h = lh & 7;
        g_rkt_all[idx] = (p < KKT)
            ? g_rkall[(long long)p * (NL * DD) + l * DD + h * 64 + d] : 0.f;
    } else {
        int idx = (int)(blk - PKA) * 256 + tid;
        if (idx >= NL * HH * RKP) return;
        int u = idx % RKP;
        int lh = idx / RKP;
        int l = lh >> 3, h = lh & 7;
        float s = 0.f;
        if (u < KKT) {
            const float* rr = g_rkall + (long long)u * (NL * DD) + l * DD + h * 64;
            const float* w = rrb + h * DH;
#pragma unroll
            for (int d = 0; d < DH; d++) s += w[d] * rr[d];
        }
        g_br_all[idx] = s;
    }
}

// ---------------- per-layer attention prep (regions B, D only) ----------------
#define PREP_B 4096
#define PREP_D (PREP_B + 8192)

__global__ void prep_kernel(const float* __restrict__ rwb, int l)
{
    int blk = blockIdx.x;
    int tid = threadIdx.x;
    if (blk < PREP_B) {
        int idx = blk * 256 + tid;
        int jq = idx & 511;
        int d  = (idx >> 9) & 63;
        int bh = idx >> 15;
        int b = bh >> 3, h = bh & 7;
        g_vt[idx] = g_wh[(long long)(b * QQ + jq) * (3 * DD) + 2 * DD + h * 64 + d];
    } else {
        int unit = tid >> 6;
        int t = tid & 63;
        int row = (blk - PREP_B) * 4 + unit;
        int kind = row >> 14;
        int r = row & 16383;
        int bh = r >> 9, iq = r & 511;
        int h = bh & 7, b = bh >> 3;
        long long base = (long long)(b * QQ + iq) * (3 * DD) + h * 64;
        float v;
        if (kind == 0) {
            v = (g_wh[base + t] + rwb[h * 64 + t]) * g_whmem_all[l * 3 * DD + DD + h * 64 + t];
        } else {
            v = rwb[h * 64 + t] * g_wh[base + DD + t];
        }
#pragma unroll
        for (int o = 16; o > 0; o >>= 1) v += __shfl_xor_sync(0xffffffffu, v, o);
        __shared__ float sh[8];
        if ((t & 31) == 0) sh[unit * 2 + (t >> 5)] = v;
        __syncthreads();
        if (t == 0) {
            float s = sh[unit * 2] + sh[unit * 2 + 1];
            if (kind == 0) g_c0[r] = s; else g_bwl[r] = s;
        }
    }
}

// ---------------- host ----------------
static void gemm(const float* A, const float* B, float* C,
                 int M, int N, int K, int ldc,
                 const float* add, int ldadd, const float* bias,
                 float alpha, int relu)
{
    if (N > 512) {
        dim3 grid((N + 127) / 128, (M + 127) / 128);
        gemm_t<128, 128, 256, 2, 2, 8><<<grid, 256>>>(A, B, C, M, N, K, ldc,
                                                      add, ldadd, bias, alpha, relu);
    } else {
        dim3 grid((N + 63) / 64, (M + 63) / 64);
        gemm_t<64, 64, 128, 5, 2, 4><<<grid, 128>>>(A, B, C, M, N, K, ldc,
                                                    add, ldadd, bias, alpha, relu);
    }
}

extern "C" void kernel_launch(void* const* d_in, const int* in_sizes, int n_in,
                              void* d_out, int out_size)
{
    const int*   ids      = (const int*)d_in[0];
    const float* emb      = (const float*)d_in[1];
    const float* emb_proj = (const float*)d_in[2];
    const float* rwb      = (const float*)d_in[3];
    const float* rrb      = (const float*)d_in[4];
    const float* qkv_w    = (const float*)d_in[5];
    const float* o_w      = (const float*)d_in[6];
    const float* rnet_w   = (const float*)d_in[7];
    const float* ln1g     = (const float*)d_in[8];
    const float* ln1b     = (const float*)d_in[9];
    const float* ff1w     = (const float*)d_in[10];
    const float* ff1b     = (const float*)d_in[11];
    const float* ff2w     = (const float*)d_in[12];
    const float* ff2b     = (const float*)d_in[13];
    const float* ln2g     = (const float*)d_in[14];
    const float* ln2b     = (const float*)d_in[15];
    const float* headw    = (const float*)d_in[16];
    const float* headb    = (const float*)d_in[17];
    float* out = (float*)d_out;

    float *p_h, *p_norm, *p_wh, *p_posemb, *p_rkall, *p_attn, *p_ff, *p_gath;
    void* tmp;
#define SYM(v, s) cudaGetSymbolAddress(&tmp, s); v = (float*)tmp;
    SYM(p_h, g_h) SYM(p_norm, g_norm) SYM(p_wh, g_wh) SYM(p_posemb, g_posemb)
    SYM(p_rkall, g_rkall) SYM(p_attn, g_attn) SYM(p_ff, g_ff) SYM(p_gath, g_gath)
#undef SYM

    const int ATTN_SMEM = (2 * 64 * SQS + UW * SQS + 64 * STS + 64 + 128 + 64) * 4;
    cudaFuncSetAttribute(attn_kernel, cudaFuncAttributeMaxDynamicSharedMemorySize, ATTN_SMEM);

    const int MQ = BB * QQ;

    // ---- input-only precomputation (once) ----
    gather_kernel<<<(MQ * DD + 255) / 256, 256>>>(ids, emb);
    posemb_kernel<<<(KKT * DD + 255) / 256, 256>>>();
    whmem_all_kernel<<<(NL * 3 * DD * 32 + 255) / 256, 256>>>(qkv_w, ln1b);
    // rk for all 12 layers in ONE wide GEMM: B = rnet_w viewed as [NL*DD, DD]
    gemm(p_posemb, rnet_w, p_rkall, KKT, NL * DD, DD, NL * DD,
         nullptr, 0, nullptr, 1.f, 0);
    packrkbr_all_kernel<<<PKB, 256>>>(rrb);
    gemm(p_gath, emb_proj, p_h, MQ, DD, DD, DD,
         nullptr, 0, nullptr, sqrtf((float)DD), 0);

    for (int l = 0; l < NL; l++) {
        const float* qkvw_l = qkv_w + (long long)l * 3 * DD * DD;
        const float* ow_l   = o_w   + (long long)l * DD * DD;
        const float* f1w_l  = ff1w  + (long long)l * DFF * DD;
        const float* f1b_l  = ff1b  + (long long)l * DFF;
        const float* f2w_l  = ff2w  + (long long)l * DD * DFF;
        const float* f2b_l  = ff2b  + (long long)l * DD;

        ln_kernel<<<MQ / 2, 256>>>(p_h, p_norm, ln1g + l * DD, ln1b + l * DD);
        gemm(p_norm, qkvw_l, p_wh, MQ, 3 * DD, DD, 3 * DD,
             nullptr, 0, nullptr, 1.f, 0);

        prep_kernel<<<PREP_D, 256>>>(rwb, l);

        attn_kernel<<<dim3(QQ / 64, BB * HH), 128, ATTN_SMEM>>>(l);

        gemm(p_attn, ow_l, p_h, MQ, DD, DD, DD,
             p_h, DD, nullptr, 1.f, 0);

        ln_kernel<<<MQ / 2, 256>>>(p_h, p_norm, ln2g + l * DD, ln2b + l * DD);
        gemm(p_norm, f1w_l, p_ff, MQ, DFF, DD, DFF,
             nullptr, 0, f1b_l, 1.f, 1);
        gemm(p_ff, f2w_l, p_h, MQ, DD, DFF, DD,
             p_h, DD, f2b_l, 1.f, 0);
    }

    gemm(p_h, headw, out, MQ, NV, DD, NV,
         nullptr, 0, headb, 1.f, 0);
}

// round 16
// speedup vs baseline: 1.2818x; 1.0420x over previous
#include <cuda_runtime.h>
#include <math.h>
#include <stdint.h>

#define BB   4
#define QQ   512
#define KKT  1024
#define DD   512
#define HH   8
#define DH   64
#define DFF  2048
#define NL   12
#define NV   332
#define MEML 512
#define UW   128
#define RKP  (KKT + UW)

// ---------------- scratch ----------------
__device__ float g_h[BB*QQ*DD];
__device__ float g_norm[BB*QQ*DD];
__device__ float g_wh[BB*QQ*3*DD];
__device__ float g_whmem_all[NL*3*DD];
__device__ float g_posemb[KKT*DD];
__device__ float g_rkall[KKT*NL*DD];
__device__ float g_rkt_all[(long)NL*HH*RKP*DH];
__device__ float g_br_all[NL*HH*RKP];
__device__ float g_vt[BB*HH*DH*QQ];
__device__ float g_c0[BB*HH*QQ];
__device__ float g_bwl[BB*HH*QQ];
__device__ float g_attn[BB*QQ*DD];
__device__ float g_ff[BB*QQ*DFF];
__device__ float g_gath[BB*QQ*DD];

__device__ __forceinline__ float to_tf32(float x) {
    uint32_t u;
    asm("cvt.rna.tf32.f32 %0, %1;" : "=r"(u) : "f"(x));
    return __uint_as_float(u);
}
__device__ __forceinline__ uint32_t to_tf32u(float x) {
    uint32_t u;
    asm("cvt.rna.tf32.f32 %0, %1;" : "=r"(u) : "f"(x));
    return u;
}

#define MMA_TF32(acc, a0,a1,a2,a3, b0,b1) \
    asm volatile("mma.sync.aligned.m16n8k8.row.col.f32.tf32.tf32.f32 " \
                 "{%0,%1,%2,%3}, {%4,%5,%6,%7}, {%8,%9}, {%0,%1,%2,%3};" \
                 : "+f"(acc[0]), "+f"(acc[1]), "+f"(acc[2]), "+f"(acc[3]) \
                 : "r"(a0), "r"(a1), "r"(a2), "r"(a3), "r"(b0), "r"(b1))

// ---------------- templated tf32 GEMM (exact R15) ----------------
template<int BMT, int BNT, int TT, int MB, int MT, int NT>
__global__ __launch_bounds__(TT, MB)
void gemm_t(const float* __restrict__ A, const float* __restrict__ B,
            float* __restrict__ C,
            int M, int N, int Kd, int ldc,
            const float* __restrict__ addsrc, int ldadd,
            const float* __restrict__ bias,
            float alpha, int relu)
{
    constexpr int R4 = TT / 4;
    constexpr int IA = (BMT + R4 - 1) / R4;
    constexpr int IB = (BNT + R4 - 1) / R4;
    constexpr int NW_N = BNT / (NT * 8);

    __shared__ float As[2][BMT][20];
    __shared__ float Bs[2][BNT][20];

    int bm = blockIdx.y * BMT, bn = blockIdx.x * BNT;
    int tid  = threadIdx.x;
    int lane = tid & 31, warp = tid >> 5;
    int g  = lane >> 2, t4 = lane & 3;
    int wm = (warp / NW_N) * (MT * 16);
    int wn = (warp % NW_N) * (NT * 8);

    int lrow = tid >> 2;
    int lkq  = (tid & 3) * 4;

    float acc[MT][NT][4];
#pragma unroll
    for (int mt = 0; mt < MT; mt++)
#pragma unroll
        for (int nt = 0; nt < NT; nt++)
#pragma unroll
            for (int q = 0; q < 4; q++) acc[mt][nt][q] = 0.f;

    float4 pa[IA], pb[IB];

    auto ldgA = [&](int k0, int it) -> float4 {
        int r = lrow + it * R4;
        int gm = bm + r;
        if (r < BMT && gm < M) return *(const float4*)&A[(long long)gm * Kd + k0 + lkq];
        return make_float4(0.f, 0.f, 0.f, 0.f);
    };
    auto ldgB = [&](int k0, int it) -> float4 {
        int r = lrow + it * R4;
        int gn = bn + r;
        if (r < BNT && gn < N) return *(const float4*)&B[(long long)gn * Kd + k0 + lkq];
        return make_float4(0.f, 0.f, 0.f, 0.f);
    };
    auto stash = [&](int buf) {
#pragma unroll
        for (int it = 0; it < IA; it++) {
            int r = lrow + it * R4;
            if (r < BMT) {
                float4 ta = make_float4(to_tf32(pa[it].x), to_tf32(pa[it].y),
                                        to_tf32(pa[it].z), to_tf32(pa[it].w));
                *(float4*)&As[buf][r][lkq] = ta;
            }
        }
#pragma unroll
        for (int it = 0; it < IB; it++) {
            int r = lrow + it * R4;
            if (r < BNT) {
                float4 tb = make_float4(to_tf32(pb[it].x), to_tf32(pb[it].y),
                                        to_tf32(pb[it].z), to_tf32(pb[it].w));
                *(float4*)&Bs[buf][r][lkq] = tb;
            }
        }
    };

    int nk = Kd >> 4;
#pragma unroll
    for (int it = 0; it < IA; it++) pa[it] = ldgA(0, it);
#pragma unroll
    for (int it = 0; it < IB; it++) pb[it] = ldgB(0, it);
    stash(0);
    __syncthreads();

    int buf = 0;
    for (int t = 0; t < nk; t++) {
        int has_next = (t + 1 < nk);
        if (has_next) {
            int k0 = (t + 1) << 4;
#pragma unroll
            for (int it = 0; it < IA; it++) pa[it] = ldgA(k0, it);
#pragma unroll
            for (int it = 0; it < IB; it++) pb[it] = ldgB(k0, it);
        }
#pragma unroll
        for (int ks = 0; ks < 16; ks += 8) {
            uint32_t af[MT][4];
#pragma unroll
            for (int mt = 0; mt < MT; mt++) {
                int m0 = wm + mt * 16 + g;
                af[mt][0] = __float_as_uint(As[buf][m0    ][ks + t4    ]);
                af[mt][1] = __float_as_uint(As[buf][m0 + 8][ks + t4    ]);
                af[mt][2] = __float_as_uint(As[buf][m0    ][ks + t4 + 4]);
                af[mt][3] = __float_as_uint(As[buf][m0 + 8][ks + t4 + 4]);
            }
#pragma unroll
            for (int nt = 0; nt < NT; nt++) {
                int n0 = wn + nt * 8 + g;
                uint32_t b0 = __float_as_uint(Bs[buf][n0][ks + t4    ]);
                uint32_t b1 = __float_as_uint(Bs[buf][n0][ks + t4 + 4]);
#pragma unroll
                for (int mt = 0; mt < MT; mt++)
                    MMA_TF32(acc[mt][nt], af[mt][0], af[mt][1], af[mt][2], af[mt][3], b0, b1);
            }
        }
        if (has_next) {
            stash(buf ^ 1);
            __syncthreads();
            buf ^= 1;
        }
    }

    auto emit = [&](int gm, int gn, float v) {
        if (gm < M && gn < N) {
            v *= alpha;
            if (bias) v += bias[gn];
            if (relu) v = fmaxf(v, 0.f);
            if (addsrc) v += addsrc[(long long)gm * ldadd + gn];
            C[(long long)gm * ldc + gn] = v;
        }
    };
#pragma unroll
    for (int mt = 0; mt < MT; mt++) {
        int r0 = bm + wm + mt * 16 + g;
#pragma unroll
        for (int nt = 0; nt < NT; nt++) {
            int c0 = bn + wn + nt * 8 + t4 * 2;
            emit(r0,     c0,     acc[mt][nt][0]);
            emit(r0,     c0 + 1, acc[mt][nt][1]);
            emit(r0 + 8, c0,     acc[mt][nt][2]);
            emit(r0 + 8, c0 + 1, acc[mt][nt][3]);
        }
    }
}

// ---------------- fused flash attention with RK ring buffer ----------------
#define SQS 68
#define STS 84

__global__ __launch_bounds__(128, 2)
void attn_kernel(int l)
{
    extern __shared__ float sm[];
    float* sK  = sm;                    // 64 x SQS
    float* sV  = sK + 64 * SQS;         // 64 x SQS
    float* sP  = sV + 64 * SQS;         // 64 x SQS (probabilities)
    float* sRK = sP + 64 * SQS;         // 2 banks x 64 x SQS, keyed by global group parity
    float* sT  = sRK + UW * SQS;        // 64 x STS
    float* sBW = sT + 64 * STS;         // 64
    float* sBR = sBW + 64;              // 128
    float* sC0 = sBR + 128;             // 64

    int it = blockIdx.x;
    int bh = blockIdx.y;
    int h = bh & 7, b = bh >> 3;
    int i0 = it * 64;
    int tid = threadIdx.x, lane = tid & 31, warp = tid >> 5;
    int g = lane >> 2, t4 = lane & 3;
    int wr = warp * 16;
    int nt0w = 6 - 2 * warp;

    const float* RKg = g_rkt_all + ((long long)l * HH + h) * RKP * DH;
    const float* BRg = g_br_all + (l * HH + h) * RKP;
    const float* Vtg = g_vt + (long long)bh * DH * QQ;

    uint32_t afQ[8][4];
    {
        long long qb = (long long)(b * QQ + i0) * (3 * DD) + h * 64;
        const float* q0 = g_wh + qb + (long long)(wr + g) * (3 * DD);
        const float* q1 = g_wh + qb + (long long)(wr + g + 8) * (3 * DD);
#pragma unroll
        for (int ks = 0; ks < 8; ks++) {
            afQ[ks][0] = to_tf32u(q0[ks * 8 + t4]);
            afQ[ks][1] = to_tf32u(q1[ks * 8 + t4]);
            afQ[ks][2] = to_tf32u(q0[ks * 8 + t4 + 4]);
            afQ[ks][3] = to_tf32u(q1[ks * 8 + t4 + 4]);
        }
    }
    if (tid < 64) sC0[tid] = g_c0[bh * QQ + i0 + tid];

    float mrow[2] = {-1e30f, -1e30f};
    float lrow[2] = {0.f, 0.f};
    float msum[2] = {0.f, 0.f};
    float O[8][4];
#pragma unroll
    for (int nt = 0; nt < 8; nt++)
#pragma unroll
        for (int q = 0; q < 4; q++) O[nt][q] = 0.f;

    int njt = it + 9;
    for (int jt = 0; jt < njt; jt++) {
        int j0 = jt * 64;
        int mem = (jt < 8);
        int ub = j0 - i0 + 448;            // 64-aligned, >= 0
        int Wg = ub >> 6;                  // base global group
        __syncthreads();
        // RK ring load: jt==0 fills both banks; else only the new top group.
        if (jt == 0) {
            int bank = (Wg + (tid >> 6)) & 1;
            const float* rs = RKg + (long long)(ub + tid) * DH;
            float* rd = sRK + (bank * 64 + (tid & 63)) * SQS;
#pragma unroll
            for (int q = 0; q < 16; q++) {
                float4 v = *(const float4*)(rs + q * 4);
                rd[q*4+0] = to_tf32(v.x); rd[q*4+1] = to_tf32(v.y);
                rd[q*4+2] = to_tf32(v.z); rd[q*4+3] = to_tf32(v.w);
            }
        } else {
            int r = tid >> 1, half = (tid & 1) * 32;
            int bank = (Wg + 1) & 1;
            const float* rs = RKg + (long long)(ub + 64 + r) * DH + half;
            float* rd = sRK + (bank * 64 + r) * SQS + half;
#pragma unroll
            for (int q = 0; q < 8; q++) {
                float4 v = *(const float4*)(rs + q * 4);
                rd[q*4+0] = to_tf32(v.x); rd[q*4+1] = to_tf32(v.y);
                rd[q*4+2] = to_tf32(v.z); rd[q*4+3] = to_tf32(v.w);
            }
        }
        if (!mem) {
            int r = tid >> 1, half = (tid & 1) * 32;
            const float* ksrc = g_wh + (long long)(b * QQ + j0 - MEML + r) * (3 * DD) + DD + h * 64 + half;
            float* kd = sK + r * SQS + half;
            const float* vsrc = Vtg + (long long)r * QQ + (j0 - MEML) + half;
            float* vd = sV + r * SQS + half;
#pragma unroll
            for (int q = 0; q < 8; q++) {
                float4 v = *(const float4*)(ksrc + q * 4);
                kd[q*4+0] = to_tf32(v.x); kd[q*4+1] = to_tf32(v.y);
                kd[q*4+2] = to_tf32(v.z); kd[q*4+3] = to_tf32(v.w);
                float4 w = *(const float4*)(vsrc + q * 4);
                vd[q*4+0] = to_tf32(w.x); vd[q*4+1] = to_tf32(w.y);
                vd[q*4+2] = to_tf32(w.z); vd[q*4+3] = to_tf32(w.w);
            }
            if (tid < 64) sBW[tid] = g_bwl[bh * QQ + (j0 - MEML) + tid];
        }
        sBR[tid] = BRg[ub + tid];
        __syncthreads();

        float ac[8][4];
        float tf[10][4];
#pragma unroll
        for (int nt = 0; nt < 8; nt++)
#pragma unroll
            for (int q = 0; q < 4; q++) ac[nt][q] = 0.f;
#pragma unroll
        for (int nt = 0; nt < 10; nt++)
#pragma unroll
            for (int q = 0; q < 4; q++) tf[nt][q] = 0.f;

#pragma unroll
        for (int ks = 0; ks < 8; ks++) {
            uint32_t a0 = afQ[ks][0], a1 = afQ[ks][1], a2 = afQ[ks][2], a3 = afQ[ks][3];
            if (!mem) {
#pragma unroll
                for (int nt = 0; nt < 8; nt++) {
                    uint32_t b0 = __float_as_uint(sK[(nt * 8 + g) * SQS + ks * 8 + t4    ]);
                    uint32_t b1 = __float_as_uint(sK[(nt * 8 + g) * SQS + ks * 8 + t4 + 4]);
                    MMA_TF32(ac[nt], a0, a1, a2, a3, b0, b1);
                }
            }
#pragma unroll
            for (int nt = 0; nt < 10; nt++) {
                int u_rel = (nt0w + nt) * 8 + g;
                int bank = (Wg + (u_rel >> 6)) & 1;
                const float* rkb = sRK + (bank * 64 + (u_rel & 63)) * SQS;
                uint32_t b0 = __float_as_uint(rkb[ks * 8 + t4    ]);
                uint32_t b1 = __float_as_uint(rkb[ks * 8 + t4 + 4]);
                MMA_TF32(tf[nt], a0, a1, a2, a3, b0, b1);
            }
        }

#pragma unroll
        for (int nt = 0; nt < 10; nt++) {
            int cr = nt * 8 + t4 * 2;
            sT[(wr + g    ) * STS + cr    ] = tf[nt][0];
            sT[(wr + g    ) * STS + cr + 1] = tf[nt][1];
            sT[(wr + g + 8) * STS + cr    ] = tf[nt][2];
            sT[(wr + g + 8) * STS + cr + 1] = tf[nt][3];
        }
        __syncwarp();

        int last = (jt == it + 8);
        float mt2[2] = {-1e30f, -1e30f};
#pragma unroll
        for (int nt = 0; nt < 8; nt++) {
            int jl0 = nt * 8 + t4 * 2;
#pragma unroll
            for (int r2 = 0; r2 < 2; r2++) {
                int il = wr + g + r2 * 8;
#pragma unroll
                for (int cc = 0; cc < 2; cc++) {
                    int jl = jl0 + cc;
                    int crel = jl - g - r2 * 8 + 15;
                    float base = mem ? sC0[il] : (ac[nt][r2*2+cc] + sBW[jl]);
                    float s = (base + sT[il * STS + crel] + sBR[jl - il + 63]) * 0.125f;
                    if (last && jl > il) s = -1e30f;
                    ac[nt][r2*2+cc] = s;
                    mt2[r2] = fmaxf(mt2[r2], s);
                }
            }
        }
#pragma unroll
        for (int r2 = 0; r2 < 2; r2++) {
            mt2[r2] = fmaxf(mt2[r2], __shfl_xor_sync(0xffffffffu, mt2[r2], 1));
            mt2[r2] = fmaxf(mt2[r2], __shfl_xor_sync(0xffffffffu, mt2[r2], 2));
        }
        float corr[2], ls[2] = {0.f, 0.f};
#pragma unroll
        for (int r2 = 0; r2 < 2; r2++) {
            float mnew = fmaxf(mrow[r2], mt2[r2]);
            corr[r2] = __expf(mrow[r2] - mnew);
            mrow[r2] = mnew;
        }
#pragma unroll
        for (int nt = 0; nt < 8; nt++)
#pragma unroll
            for (int r2 = 0; r2 < 2; r2++)
#pragma unroll
                for (int cc = 0; cc < 2; cc++) {
                    float e = __expf(ac[nt][r2*2+cc] - mrow[r2]);
                    ac[nt][r2*2+cc] = e;
                    ls[r2] += e;
                }
#pragma unroll
        for (int r2 = 0; r2 < 2; r2++) {
            ls[r2] += __shfl_xor_sync(0xffffffffu, ls[r2], 1);
            ls[r2] += __shfl_xor_sync(0xffffffffu, ls[r2], 2);
            lrow[r2] = lrow[r2] * corr[r2] + ls[r2];
            msum[r2] *= corr[r2];
            if (mem) msum[r2] += ls[r2];
        }
#pragma unroll
        for (int nt = 0; nt < 8; nt++)
#pragma unroll
            for (int q = 0; q < 4; q++) O[nt][q] *= corr[q >> 1];

        if (!mem) {
#pragma unroll
            for (int nt = 0; nt < 8; nt++) {
                int c = nt * 8 + t4 * 2;
                sP[(wr + g    ) * SQS + c    ] = to_tf32(ac[nt][0]);
                sP[(wr + g    ) * SQS + c + 1] = to_tf32(ac[nt][1]);
                sP[(wr + g + 8) * SQS + c    ] = to_tf32(ac[nt][2]);
                sP[(wr + g + 8) * SQS + c + 1] = to_tf32(ac[nt][3]);
            }
            __syncwarp();
#pragma unroll
            for (int ks = 0; ks < 8; ks++) {
                uint32_t a0 = __float_as_uint(sP[(wr + g    ) * SQS + ks * 8 + t4    ]);
                uint32_t a1 = __float_as_uint(sP[(wr + g + 8) * SQS + ks * 8 + t4    ]);
                uint32_t a2 = __float_as_uint(sP[(wr + g    ) * SQS + ks * 8 + t4 + 4]);
                uint32_t a3 = __float_as_uint(sP[(wr + g + 8) * SQS + ks * 8 + t4 + 4]);
#pragma unroll
                for (int nt = 0; nt < 8; nt++) {
                    uint32_t b0 = __float_as_uint(sV[(nt * 8 + g) * SQS + ks * 8 + t4    ]);
                    uint32_t b1 = __float_as_uint(sV[(nt * 8 + g) * SQS + ks * 8 + t4 + 4]);
                    MMA_TF32(O[nt], a0, a1, a2, a3, b0, b1);
                }
            }
        }
    }

    float inv0 = 1.f / lrow[0], inv1 = 1.f / lrow[1];
    const float* vm = g_whmem_all + l * 3 * DD + 2 * DD + h * 64;
    long long r0 = (long long)(b * QQ + i0 + wr + g) * DD + h * 64;
    long long r1 = (long long)(b * QQ + i0 + wr + g + 8) * DD + h * 64;
#pragma unroll
    for (int nt = 0; nt < 8; nt++) {
        int c = nt * 8 + t4 * 2;
        float v0 = vm[c], v1 = vm[c + 1];
        g_attn[r0 + c]     = (O[nt][0] + msum[0] * v0) * inv0;
        g_attn[r0 + c + 1] = (O[nt][1] + msum[0] * v1) * inv0;
        g_attn[r1 + c]     = (O[nt][2] + msum[1] * v0) * inv1;
        g_attn[r1 + c + 1] = (O[nt][3] + msum[1] * v1) * inv1;
    }
}

// ---------------- layernorm ----------------
__global__ void ln_kernel(const float* __restrict__ x, float* __restrict__ y,
                          const float* __restrict__ g, const float* __restrict__ b)
{
    int tid = threadIdx.x;
    int half = tid >> 7;
    int t = tid & 127;
    int row = blockIdx.x * 2 + half;
    const float* xr = x + (long long)row * DD;
    float* yr = y + (long long)row * DD;
    float4 v = *(const float4*)(xr + t * 4);
    float s = v.x + v.y + v.z + v.w;
    float s2 = v.x*v.x + v.y*v.y + v.z*v.z + v.w*v.w;
    __shared__ float sh[2][8];
    __shared__ float stats[2][2];
#pragma unroll
    for (int o = 16; o > 0; o >>= 1) {
        s  += __shfl_xor_sync(0xffffffffu, s,  o);
        s2 += __shfl_xor_sync(0xffffffffu, s2, o);
    }
    int w4 = (tid >> 5) & 3;
    if ((tid & 31) == 0) { sh[half][w4] = s; sh[half][w4 + 4] = s2; }
    __syncthreads();
    if (t == 0) {
        float S = sh[half][0] + sh[half][1] + sh[half][2] + sh[half][3];
        float S2 = sh[half][4] + sh[half][5] + sh[half][6] + sh[half][7];
        float mu = S / DD;
        float var = S2 / DD - mu * mu;
        stats[half][0] = mu;
        stats[half][1] = rsqrtf(var + 1e-3f);
    }
    __syncthreads();
    float mu = stats[half][0], rs = stats[half][1];
    float4 gv = *(const float4*)(g + t * 4);
    float4 bv = *(const float4*)(b + t * 4);
    float4 o;
    o.x = (v.x - mu) * rs * gv.x + bv.x;
    o.y = (v.y - mu) * rs * gv.y + bv.y;
    o.z = (v.z - mu) * rs * gv.z + bv.z;
    o.w = (v.w - mu) * rs * gv.w + bv.w;
    *(float4*)(yr + t * 4) = o;
}

__global__ void whmem_all_kernel(const float* __restrict__ qkvw, const float* __restrict__ ln1b)
{
    int gw = (blockIdx.x * 256 + threadIdx.x) >> 5;
    int lane = threadIdx.x & 31;
    if (gw >= NL * 3 * DD) return;
    int l = gw / (3 * DD), n = gw % (3 * DD);
    const float* wr = qkvw + ((long long)l * 3 * DD + n) * DD;
    const float* lb = ln1b + l * DD;
    float s = 0.f;
#pragma unroll
    for (int i = 0; i < 16; i++) s += lb[lane + i * 32] * wr[lane + i * 32];
#pragma unroll
    for (int o = 16; o > 0; o >>= 1) s += __shfl_xor_sync(0xffffffffu, s, o);
    if (lane == 0) g_whmem_all[gw] = s;
}

__global__ void posemb_kernel()
{
    int idx = blockIdx.x * blockDim.x + threadIdx.x;
    if (idx >= KKT * DD) return;
    int p = idx / DD, c = idx % DD;
    float pos = (float)(KKT - 1 - p);
    int k = (c < 256) ? c : (c - 256);
    float invf = powf(10000.0f, -((float)(2 * k)) / 512.0f);
    float a = pos * invf;
    g_posemb[idx] = (c < 256) ? sinf(a) : cosf(a);
}

__global__ void gather_kernel(const int* __restrict__ ids, const float* __restrict__ emb)
{
    int idx = blockIdx.x * blockDim.x + threadIdx.x;
    if (idx >= BB * QQ * DD) return;
    int m = idx / DD, c = idx % DD;
    g_gath[idx] = emb[(long long)ids[m] * DD + c];
}

// ---- batched rk pack + br for all layers (runs once) ----
#define PKA 27648
#define PKB (PKA + 432)

__global__ void packrkbr_all_kernel(const float* __restrict__ rrb)
{
    long long blk = blockIdx.x;
    int tid = threadIdx.x;
    if (blk < PKA) {
        long long idx = blk * 256 + tid;
        int d = (int)(idx & 63);
        int p = (int)((idx >> 6) % RKP);
        int lh = (int)(idx / ((long long)RKP * DH));
        int l = lh >> 3, h = lh & 7;
        g_rkt_all[idx] = (p < KKT)
            ? g_rkall[(long long)p * (NL * DD) + l * DD + h * 64 + d] : 0.f;
    } else {
        int idx = (int)(blk - PKA) * 256 + tid;
        if (idx >= NL * HH * RKP) return;
        int u = idx % RKP;
        int lh = idx / RKP;
        int l = lh >> 3, h = lh & 7;
        float s = 0.f;
        if (u < KKT) {
            const float* rr = g_rkall + (long long)u * (NL * DD) + l * DD + h * 64;
            const float* w = rrb + h * DH;
#pragma unroll
            for (int d = 0; d < DH; d++) s += w[d] * rr[d];
        }
        g_br_all[idx] = s;
    }
}

// ---------------- per-layer attention prep (regions B, D) ----------------
#define PREP_B 4096
#define PREP_D (PREP_B + 8192)

__global__ void prep_kernel(const float* __restrict__ rwb, int l)
{
    int blk = blockIdx.x;
    int tid = threadIdx.x;
    if (blk < PREP_B) {
        int idx = blk * 256 + tid;
        int jq = idx & 511;
        int d  = (idx >> 9) & 63;
        int bh = idx >> 15;
        int b = bh >> 3, h = bh & 7;
        g_vt[idx] = g_wh[(long long)(b * QQ + jq) * (3 * DD) + 2 * DD + h * 64 + d];
    } else {
        int unit = tid >> 6;
        int t = tid & 63;
        int row = (blk - PREP_B) * 4 + unit;
        int kind = row >> 14;
        int r = row & 16383;
        int bh = r >> 9, iq = r & 511;
        int h = bh & 7, b = bh >> 3;
        long long base = (long long)(b * QQ + iq) * (3 * DD) + h * 64;
        float v;
        if (kind == 0) {
            v = (g_wh[base + t] + rwb[h * 64 + t]) * g_whmem_all[l * 3 * DD + DD + h * 64 + t];
        } else {
            v = rwb[h * 64 + t] * g_wh[base + DD + t];
        }
#pragma unroll
        for (int o = 16; o > 0; o >>= 1) v += __shfl_xor_sync(0xffffffffu, v, o);
        __shared__ float sh[8];
        if ((t & 31) == 0) sh[unit * 2 + (t >> 5)] = v;
        __syncthreads();
        if (t == 0) {
            float s = sh[unit * 2] + sh[unit * 2 + 1];
            if (kind == 0) g_c0[r] = s; else g_bwl[r] = s;
        }
    }
}

// ---------------- host ----------------
static void gemm(const float* A, const float* B, float* C,
                 int M, int N, int K, int ldc,
                 const float* add, int ldadd, const float* bias,
                 float alpha, int relu)
{
    if (N > 512) {
        dim3 grid((N + 127) / 128, (M + 127) / 128);
        gemm_t<128, 128, 256, 2, 2, 8><<<grid, 256>>>(A, B, C, M, N, K, ldc,
                                                      add, ldadd, bias, alpha, relu);
    } else {
        dim3 grid((N + 63) / 64, (M + 63) / 64);
        gemm_t<64, 64, 128, 5, 2, 4><<<grid, 128>>>(A, B, C, M, N, K, ldc,
                                                    add, ldadd, bias, alpha, relu);
    }
}

extern "C" void kernel_launch(void* const* d_in, const int* in_sizes, int n_in,
                              void* d_out, int out_size)
{
    const int*   ids      = (const int*)d_in[0];
    const float* emb      = (const float*)d_in[1];
    const float* emb_proj = (const float*)d_in[2];
    const float* rwb      = (const float*)d_in[3];
    const float* rrb      = (const float*)d_in[4];
    const float* qkv_w    = (const float*)d_in[5];
    const float* o_w      = (const float*)d_in[6];
    const float* rnet_w   = (const float*)d_in[7];
    const float* ln1g     = (const float*)d_in[8];
    const float* ln1b     = (const float*)d_in[9];
    const float* ff1w     = (const float*)d_in[10];
    const float* ff1b     = (const float*)d_in[11];
    const float* ff2w     = (const float*)d_in[12];
    const float* ff2b     = (const float*)d_in[13];
    const float* ln2g     = (const float*)d_in[14];
    const float* ln2b     = (const float*)d_in[15];
    const float* headw    = (const float*)d_in[16];
    const float* headb    = (const float*)d_in[17];
    float* out = (float*)d_out;

    float *p_h, *p_norm, *p_wh, *p_posemb, *p_rkall, *p_attn, *p_ff, *p_gath;
    void* tmp;
#define SYM(v, s) cudaGetSymbolAddress(&tmp, s); v = (float*)tmp;
    SYM(p_h, g_h) SYM(p_norm, g_norm) SYM(p_wh, g_wh) SYM(p_posemb, g_posemb)
    SYM(p_rkall, g_rkall) SYM(p_attn, g_attn) SYM(p_ff, g_ff) SYM(p_gath, g_gath)
#undef SYM

    const int ATTN_SMEM = (3 * 64 * SQS + UW * SQS + 64 * STS + 64 + 128 + 64) * 4;
    cudaFuncSetAttribute(attn_kernel, cudaFuncAttributeMaxDynamicSharedMemorySize, ATTN_SMEM);

    const int MQ = BB * QQ;

    // ---- input-only precomputation (once) ----
    gather_kernel<<<(MQ * DD + 255) / 256, 256>>>(ids, emb);
    posemb_kernel<<<(KKT * DD + 255) / 256, 256>>>();
    whmem_all_kernel<<<(NL * 3 * DD * 32 + 255) / 256, 256>>>(qkv_w, ln1b);
    gemm(p_posemb, rnet_w, p_rkall, KKT, NL * DD, DD, NL * DD,
         nullptr, 0, nullptr, 1.f, 0);
    packrkbr_all_kernel<<<PKB, 256>>>(rrb);
    gemm(p_gath, emb_proj, p_h, MQ, DD, DD, DD,
         nullptr, 0, nullptr, sqrtf((float)DD), 0);

    for (int l = 0; l < NL; l++) {
        const float* qkvw_l = qkv_w + (long long)l * 3 * DD * DD;
        const float* ow_l   = o_w   + (long long)l * DD * DD;
        const float* f1w_l  = ff1w  + (long long)l * DFF * DD;
        const float* f1b_l  = ff1b  + (long long)l * DFF;
        const float* f2w_l  = ff2w  + (long long)l * DD * DFF;
        const float* f2b_l  = ff2b  + (long long)l * DD;

        ln_kernel<<<MQ / 2, 256>>>(p_h, p_norm, ln1g + l * DD, ln1b + l * DD);
        gemm(p_norm, qkvw_l, p_wh, MQ, 3 * DD, DD, 3 * DD,
             nullptr, 0, nullptr, 1.f, 0);

        prep_kernel<<<PREP_D, 256>>>(rwb, l);

        attn_kernel<<<dim3(QQ / 64, BB * HH), 128, ATTN_SMEM>>>(l);

        gemm(p_attn, ow_l, p_h, MQ, DD, DD, DD,
             p_h, DD, nullptr, 1.f, 0);

        ln_kernel<<<MQ / 2, 256>>>(p_h, p_norm, ln2g + l * DD, ln2b + l * DD);
        gemm(p_norm, f1w_l, p_ff, MQ, DFF, DD, DFF,
             nullptr, 0, f1b_l, 1.f, 1);
        gemm(p_ff, f2w_l, p_h, MQ, DD, DFF, DD,
             p_h, DD, f2b_l, 1.f, 0);
    }

    gemm(p_h, headw, out, MQ, NV, DD, NV,
         nullptr, 0, headb, 1.f, 0);
}